// round 12
// baseline (speedup 1.0000x reference)
#include <cuda_runtime.h>
#include <math.h>

#define FULLMASK 0xffffffffu

#define BB   2
#define NN   2048
#define HH   8
#define HID  128
#define VD   16
#define BN   (BB * NN)
// locality=5 -> pos=0.05*2047=102.35 -> need 103rd smallest (0-indexed 102)
#define KTH  103

// GEMM smem: Ws [128][64] f32 (32KB) + As [32][128] f32 (16KB) = 48KB
#define GEMM_SMEM (32768 + 16384)
// Attention smem: head-paired v chunk: 512 rows x 18 ull (144B) = 73.7KB -> 2 CTAs/SM
#define VCHUNK 512
#define VSTRU  18
#define ATTN_SMEM (VCHUNK * VSTRU * 8)

typedef unsigned long long ull;

// ---------------- scratch (device globals; no allocation) ----------------
__device__ float  g_en[BN * HID];
__device__ float  g_x [BN * HID];
__device__ float  g_h [BN * HID];
__device__ float  g_t [BN * HID];
__device__ float  g_r [BN * HID];
__device__ float  g_v [BN * HID];
__device__ float2 g_rowstats[BN];

// ---------------- f32x2 packed helpers ----------------
__device__ __forceinline__ ull pack2(float x, float y) {
    ull r;
    asm("mov.b64 %0, {%1, %2};" : "=l"(r) : "r"(__float_as_uint(x)), "r"(__float_as_uint(y)));
    return r;
}
__device__ __forceinline__ void unpack2(ull u, float& x, float& y) {
    unsigned a, b;
    asm("mov.b64 {%0, %1}, %2;" : "=r"(a), "=r"(b) : "l"(u));
    x = __uint_as_float(a); y = __uint_as_float(b);
}
__device__ __forceinline__ ull fma2(ull a, ull b, ull c) {
    ull d;
    asm("fma.rn.f32x2 %0, %1, %2, %3;" : "=l"(d) : "l"(a), "l"(b), "l"(c));
    return d;
}
__device__ __forceinline__ ull add2(ull a, ull b) {
    ull d;
    asm("add.rn.f32x2 %0, %1, %2;" : "=l"(d) : "l"(a), "l"(b));
    return d;
}
__device__ __forceinline__ float ex2f(float x) {
    float r;
    asm("ex2.approx.f32 %0, %1;" : "=f"(r) : "f"(x));
    return r;
}

__device__ __forceinline__ float gelu_f(float x) {
    // exact (erf) gelu, matching jax.nn.gelu(approximate=False)
    return 0.5f * x * (1.0f + erff(x * 0.70710678118654752f));
}

// ---------------- per-row order statistics of m_dist ----------------
__global__ void rowstats_kernel(const float* __restrict__ md, float2* __restrict__ rs) {
    int warp = threadIdx.x >> 5, lane = threadIdx.x & 31;
    int row = blockIdx.x * 8 + warp;
    const float* p = md + (size_t)row * NN + lane;
    unsigned mu[64];
    float mn = 1e30f;
#pragma unroll
    for (int i = 0; i < 64; ++i) {
        float x = p[i * 32];
        mn = fminf(mn, x);
        mu[i] = __float_as_uint(x);
    }
#pragma unroll
    for (int off = 16; off; off >>= 1)
        mn = fminf(mn, __shfl_xor_sync(FULLMASK, mn, off));

    unsigned lo = 0u, hi = 0x3F800000u;  // bit patterns of [0,1)
    while (hi - lo > 1u) {
        unsigned mid = (lo + hi) >> 1;
        int c = 0;
#pragma unroll
        for (int i = 0; i < 64; ++i) c += (mu[i] <= mid) ? 1 : 0;
        c = __reduce_add_sync(FULLMASK, c);
        if (c >= KTH) hi = mid; else lo = mid;
    }
    if (lane == 0) rs[row] = make_float2(mn, __uint_as_float(hi));
}

// ---------------- encoder: gelu(inputs @ en_W + en_b), K=3 ----------------
__global__ void enc_kernel(const float* __restrict__ inp, const float* __restrict__ W,
                           const float* __restrict__ bvec, float* __restrict__ out) {
    int token = blockIdx.x, c = threadIdx.x;
    float x0 = inp[token * 3 + 0];
    float x1 = inp[token * 3 + 1];
    float x2 = inp[token * 3 + 2];
    float s = bvec[c];
    s = fmaf(x0, W[c], s);
    s = fmaf(x1, W[HID + c], s);
    s = fmaf(x2, W[2 * HID + c], s);
    out[(size_t)token * HID + c] = gelu_f(s);
}

// ---------------- GEMM body: 32 rows x 64 cols per CTA ----------------
// vproj: W is head-major (H, HID, VD); logical col c maps to
// W[(c>>4)*HID*VD + k*VD + (c&15)] — 4 consecutive cols stay contiguous.
__device__ __forceinline__ void gemm3_body(
    const float* __restrict__ A, const float* __restrict__ W,
    const float* __restrict__ bias, const float* __restrict__ res,
    float* __restrict__ out, int act, int vproj, float* sm)
{
    float* Ws = sm;              // [128][64]
    float* As = sm + 128 * 64;   // [32][128]

    int tid = threadIdx.x, lane = tid & 31, warp = tid >> 5;
    int row0 = blockIdx.x * 32;
    int cbase = blockIdx.y * 64;

    if (vproj) {
#pragma unroll
        for (int idx = tid; idx < 128 * 16; idx += 256) {
            int k = idx >> 4, q = idx & 15;
            int c0 = cbase + q * 4;
            const float* src = W + (size_t)(c0 >> 4) * (HID * VD) + k * VD + (c0 & 15);
            *(float4*)(Ws + k * 64 + q * 4) = *(const float4*)src;
        }
    } else {
#pragma unroll
        for (int idx = tid; idx < 128 * 16; idx += 256) {
            int k = idx >> 4, q = idx & 15;
            *(float4*)(Ws + k * 64 + q * 4) = *(const float4*)(W + (size_t)k * HID + cbase + q * 4);
        }
    }
#pragma unroll
    for (int idx = tid; idx < 32 * 32; idx += 256) {
        int r = idx >> 5, q = idx & 31;
        *(float4*)(As + r * HID + q * 4) = *(const float4*)(A + (size_t)(row0 + r) * HID + q * 4);
    }
    __syncthreads();

    ull acc[4] = {0ull, 0ull, 0ull, 0ull};
    const ull* Wu = (const ull*)Ws;          // [k][32]
    const float* a0 = As + warp * 4 * HID;

#pragma unroll 8
    for (int k = 0; k < HID; ++k) {
        ull wp = Wu[k * 32 + lane];
        float x0 = a0[0 * HID + k];
        float x1 = a0[1 * HID + k];
        float x2 = a0[2 * HID + k];
        float x3 = a0[3 * HID + k];
        acc[0] = fma2(pack2(x0, x0), wp, acc[0]);
        acc[1] = fma2(pack2(x1, x1), wp, acc[1]);
        acc[2] = fma2(pack2(x2, x2), wp, acc[2]);
        acc[3] = fma2(pack2(x3, x3), wp, acc[3]);
    }

    float b0 = 0.f, b1 = 0.f;
    if (bias) {
        float2 bv = *(const float2*)(bias + cbase + 2 * lane);
        b0 = bv.x; b1 = bv.y;
    }
#pragma unroll
    for (int i = 0; i < 4; ++i) {
        int row = row0 + warp * 4 + i;
        float o0, o1;
        unpack2(acc[i], o0, o1);
        o0 += b0; o1 += b1;
        if (res) {
            float2 rv = *(const float2*)(res + (size_t)row * HID + cbase + 2 * lane);
            o0 += rv.x; o1 += rv.y;
        }
        if (act) { o0 = gelu_f(o0); o1 = gelu_f(o1); }
        *(float2*)(out + (size_t)row * HID + cbase + 2 * lane) = make_float2(o0, o1);
    }
}

__global__ void __launch_bounds__(256) gemm3_kernel(
    const float* __restrict__ A, const float* __restrict__ W,
    const float* __restrict__ bias, const float* __restrict__ res,
    float* __restrict__ out, int act)
{
    extern __shared__ float sm[];
    gemm3_body(A, W, bias, res, out, act, 0, sm);
}

// paired GEMM on the same A. z=0: v-proj from head-major Whead (no bias).
// z=1: skip-proj out1 = A@W1 + b1.
__global__ void __launch_bounds__(256) gemm3p_kernel(
    const float* __restrict__ A,
    const float* __restrict__ Whead, float* __restrict__ out0,
    const float* __restrict__ W1, const float* __restrict__ b1,
    float* __restrict__ out1)
{
    extern __shared__ float sm[];
    if (blockIdx.z == 0) gemm3_body(A, Whead, nullptr, nullptr, out0, 0, 1, sm);
    else                 gemm3_body(A, W1,    b1,      nullptr, out1, 0, 0, sm);
}

// ---------------- fused percentile-softmax attention + gelu (head-paired) --
// One CTA per (32 rows, head-PAIR hp, batch b). Both heads share the same m
// row and mask predicate (sd = m*r^2 monotone per head), so each m LDG,
// FSETP, and loop step serves 2 heads. v interleaved in smem as
// ull(v_hA[j][d], v_hB[j][d]); acc fma2 computes both heads per dim.
// Lane = (jl 0..15, dh 0..1 dim half); acc[4 rows][8 dims] ull.
// Stride 18 ull (144B) rows: quarter-warp LDS.128 starts {0,4,..,28} banks ->
// conflict-free. 73.7KB smem -> 2 CTAs/SM. Depth-2 m ring (~340cyc step).
template <int MASKED>
__global__ void __launch_bounds__(256, 2) attn11_kernel(
    const float* __restrict__ md, const float* __restrict__ v,
    const float* __restrict__ rvec, const float2* __restrict__ rs,
    float* __restrict__ out)
{
    extern __shared__ ull vsu[];   // [VCHUNK][18]
    int b = blockIdx.z, hp = blockIdx.y;
    int hA = 2 * hp, hB = 2 * hp + 1;
    float rA = rvec[hA], rB = rvec[hB];
    float r2A = rA * rA, r2B = rB * rB;
    const float L2E = 1.4426950408889634f;
    float nr2lA = -r2A * L2E, nr2lB = -r2B * L2E;

    int tid = threadIdx.x;
    int lane = tid & 31, warp = tid >> 5;
    int jl = lane & 15, dh = lane >> 4;
    int i0 = blockIdx.x * 32 + warp * 4;

    float msA[4], msB[4], s102[4];
    ull wsum2[4];                   // packed (wsumA, wsumB) per row
    ull acc[4][8];
#pragma unroll
    for (int g = 0; g < 4; ++g) {
        float2 st = rs[b * NN + i0 + g];
        msA[g] = (st.x * r2A) * L2E;  // st.x*r2 == min_j(sd) exactly (monotone)
        msB[g] = (st.x * r2B) * L2E;
        s102[g] = st.y;
        wsum2[g] = 0ull;
#pragma unroll
        for (int d = 0; d < 8; ++d) acc[g][d] = 0ull;
    }

    const float* mrow = md + ((size_t)b * NN + i0) * NN + jl;

    // prime depth-2 m prefetch ring over 16-wide steps (0..127)
    float mr[4][2];
#pragma unroll
    for (int d = 0; d < 2; ++d)
#pragma unroll
        for (int g = 0; g < 4; ++g) mr[g][d] = mrow[(size_t)g * NN + 16 * d];

    const float* vgA = v + (size_t)b * NN * HID + hA * VD;
    const float* vgB = v + (size_t)b * NN * HID + hB * VD;

    for (int c = 0; c < NN / VCHUNK; ++c) {
        __syncthreads();
        // stage interleaved v chunk: vsu[j][d] = (vA[j][d], vB[j][d])
        for (int idx = tid; idx < VCHUNK * 8; idx += 256) {
            int jj = idx >> 3, q = (idx & 7) << 1;   // dims q, q+1
            size_t go = (size_t)(c * VCHUNK + jj) * HID + q;
            float2 a = *(const float2*)(vgA + go);
            float2 bb = *(const float2*)(vgB + go);
            ull* dst = vsu + jj * VSTRU + q;
            dst[0] = pack2(a.x, bb.x);
            dst[1] = pack2(a.y, bb.y);
        }
        __syncthreads();

#pragma unroll 4
        for (int t = 0; t < VCHUNK / 16; ++t) {
            int gt = c * (VCHUNK / 16) + t;
            int slot = gt & 1;

            // 8 dims x 2 heads = 8 ull = 4 aligned LDS.128
            const ulonglong2* vrow = (const ulonglong2*)(vsu + (16 * t + jl) * VSTRU + dh * 8);
            ulonglong2 p0 = vrow[0], p1 = vrow[1], p2 = vrow[2], p3 = vrow[3];
            ull v0 = p0.x, v1 = p0.y, v2 = p1.x, v3 = p1.y;
            ull v4 = p2.x, v5 = p2.y, v6 = p3.x, v7 = p3.y;

            float m0 = mr[0][slot], m1 = mr[1][slot], m2 = mr[2][slot], m3 = mr[3][slot];

            // prefetch m for step gt+2 (clamped; tail prefetches unused)
            int tp = gt + 2; if (tp > NN / 16 - 1) tp = NN / 16 - 1;
            mr[0][slot] = mrow[0 * (size_t)NN + 16 * tp];
            mr[1][slot] = mrow[1 * (size_t)NN + 16 * tp];
            mr[2][slot] = mrow[2 * (size_t)NN + 16 * tp];
            mr[3][slot] = mrow[3 * (size_t)NN + 16 * tp];

            ull wp0, wp1, wp2, wp3;
            {
                float eA = ex2f(fmaf(m0, nr2lA, msA[0]));
                float eB = ex2f(fmaf(m0, nr2lB, msB[0]));
                ull w = pack2(eA, eB);
                wp0 = MASKED ? ((m0 <= s102[0]) ? w : 0ull) : w;
            }
            {
                float eA = ex2f(fmaf(m1, nr2lA, msA[1]));
                float eB = ex2f(fmaf(m1, nr2lB, msB[1]));
                ull w = pack2(eA, eB);
                wp1 = MASKED ? ((m1 <= s102[1]) ? w : 0ull) : w;
            }
            {
                float eA = ex2f(fmaf(m2, nr2lA, msA[2]));
                float eB = ex2f(fmaf(m2, nr2lB, msB[2]));
                ull w = pack2(eA, eB);
                wp2 = MASKED ? ((m2 <= s102[2]) ? w : 0ull) : w;
            }
            {
                float eA = ex2f(fmaf(m3, nr2lA, msA[3]));
                float eB = ex2f(fmaf(m3, nr2lB, msB[3]));
                ull w = pack2(eA, eB);
                wp3 = MASKED ? ((m3 <= s102[3]) ? w : 0ull) : w;
            }
            wsum2[0] = add2(wsum2[0], wp0);
            wsum2[1] = add2(wsum2[1], wp1);
            wsum2[2] = add2(wsum2[2], wp2);
            wsum2[3] = add2(wsum2[3], wp3);

            acc[0][0] = fma2(wp0, v0, acc[0][0]);  acc[0][1] = fma2(wp0, v1, acc[0][1]);
            acc[0][2] = fma2(wp0, v2, acc[0][2]);  acc[0][3] = fma2(wp0, v3, acc[0][3]);
            acc[0][4] = fma2(wp0, v4, acc[0][4]);  acc[0][5] = fma2(wp0, v5, acc[0][5]);
            acc[0][6] = fma2(wp0, v6, acc[0][6]);  acc[0][7] = fma2(wp0, v7, acc[0][7]);

            acc[1][0] = fma2(wp1, v0, acc[1][0]);  acc[1][1] = fma2(wp1, v1, acc[1][1]);
            acc[1][2] = fma2(wp1, v2, acc[1][2]);  acc[1][3] = fma2(wp1, v3, acc[1][3]);
            acc[1][4] = fma2(wp1, v4, acc[1][4]);  acc[1][5] = fma2(wp1, v5, acc[1][5]);
            acc[1][6] = fma2(wp1, v6, acc[1][6]);  acc[1][7] = fma2(wp1, v7, acc[1][7]);

            acc[2][0] = fma2(wp2, v0, acc[2][0]);  acc[2][1] = fma2(wp2, v1, acc[2][1]);
            acc[2][2] = fma2(wp2, v2, acc[2][2]);  acc[2][3] = fma2(wp2, v3, acc[2][3]);
            acc[2][4] = fma2(wp2, v4, acc[2][4]);  acc[2][5] = fma2(wp2, v5, acc[2][5]);
            acc[2][6] = fma2(wp2, v6, acc[2][6]);  acc[2][7] = fma2(wp2, v7, acc[2][7]);

            acc[3][0] = fma2(wp3, v0, acc[3][0]);  acc[3][1] = fma2(wp3, v1, acc[3][1]);
            acc[3][2] = fma2(wp3, v2, acc[3][2]);  acc[3][3] = fma2(wp3, v3, acc[3][3]);
            acc[3][4] = fma2(wp3, v4, acc[3][4]);  acc[3][5] = fma2(wp3, v5, acc[3][5]);
            acc[3][6] = fma2(wp3, v6, acc[3][6]);  acc[3][7] = fma2(wp3, v7, acc[3][7]);
        }
    }

    // butterfly reduce across the 16 jl slots (xor bits 0..3 stays in dh half)
#pragma unroll
    for (int off = 8; off; off >>= 1) {
#pragma unroll
        for (int g = 0; g < 4; ++g) {
            ull o = __shfl_xor_sync(FULLMASK, wsum2[g], off);
            wsum2[g] = add2(wsum2[g], o);
#pragma unroll
            for (int d = 0; d < 8; ++d) {
                ull a = __shfl_xor_sync(FULLMASK, acc[g][d], off);
                acc[g][d] = add2(acc[g][d], a);
            }
        }
    }

    if (jl < 4) {
        int g = jl;
        float wA, wB;
        unpack2(wsum2[g], wA, wB);
        float invA = 1.0f / wA, invB = 1.0f / wB;
        float oA[8], oB[8];
#pragma unroll
        for (int d = 0; d < 8; ++d) {
            float a, bb;
            unpack2(acc[g][d], a, bb);
            oA[d] = gelu_f(a * invA);
            oB[d] = gelu_f(bb * invB);
        }
        float* base = out + (size_t)(b * NN + i0 + g) * HID;
        float* dA = base + hA * VD + dh * 8;
        float* dB = base + hB * VD + dh * 8;
        *(float4*)(dA + 0) = make_float4(oA[0], oA[1], oA[2], oA[3]);
        *(float4*)(dA + 4) = make_float4(oA[4], oA[5], oA[6], oA[7]);
        *(float4*)(dB + 0) = make_float4(oB[0], oB[1], oB[2], oB[3]);
        *(float4*)(dB + 4) = make_float4(oB[4], oB[5], oB[6], oB[7]);
    }
}

// ---------------- final 128 -> 1 projection ----------------
__global__ void final_kernel(const float* __restrict__ t, const float* __restrict__ W,
                             const float* __restrict__ bvec, float* __restrict__ out) {
    int warp = threadIdx.x >> 5, lane = threadIdx.x & 31;
    int token = blockIdx.x * 8 + warp;
    const float* p = t + (size_t)token * HID;
    float s = 0.f;
#pragma unroll
    for (int i = 0; i < 4; ++i) s = fmaf(p[lane + 32 * i], W[lane + 32 * i], s);
#pragma unroll
    for (int off = 16; off; off >>= 1) s += __shfl_xor_sync(FULLMASK, s, off);
    if (lane == 0) out[token] = s + bvec[0];
}

// ---------------- orchestration ----------------
static float* symf(const void* sym) {
    void* p = nullptr;
    cudaGetSymbolAddress(&p, sym);
    return (float*)p;
}

extern "C" void kernel_launch(void* const* d_in, const int* in_sizes, int n_in,
                              void* d_out, int out_size) {
    const float* md      = (const float*)d_in[0];
    const float* inputs  = (const float*)d_in[1];
    const float* en_W    = (const float*)d_in[2];
    const float* en_b    = (const float*)d_in[3];
    const float* down_r  = (const float*)d_in[4];
    const float* down_w  = (const float*)d_in[5];
    const float* mlp1_W1 = (const float*)d_in[6];
    const float* mlp1_b1 = (const float*)d_in[7];
    const float* mlp1_W2 = (const float*)d_in[8];
    const float* mlp1_b2 = (const float*)d_in[9];
    const float* w1_W    = (const float*)d_in[10];
    const float* w1_b    = (const float*)d_in[11];
    const float* pa_r    = (const float*)d_in[12];
    const float* pa_w    = (const float*)d_in[13];
    const float* blk_W1  = (const float*)d_in[14];
    const float* blk_b1  = (const float*)d_in[15];
    const float* blk_W2  = (const float*)d_in[16];
    const float* blk_b2  = (const float*)d_in[17];
    const float* wi_W    = (const float*)d_in[18];
    const float* wi_b    = (const float*)d_in[19];
    const float* up_r    = (const float*)d_in[20];
    const float* up_w    = (const float*)d_in[21];
    const float* mlp2_W1 = (const float*)d_in[22];
    const float* mlp2_b1 = (const float*)d_in[23];
    const float* mlp2_W2 = (const float*)d_in[24];
    const float* mlp2_b2 = (const float*)d_in[25];
    const float* w2_W    = (const float*)d_in[26];
    const float* w2_b    = (const float*)d_in[27];
    const float* de_W1   = (const float*)d_in[28];
    const float* de_b1   = (const float*)d_in[29];
    const float* de_W2   = (const float*)d_in[30];
    const float* de_b2   = (const float*)d_in[31];
    float* outp = (float*)d_out;

    float*  en = symf(g_en);
    float*  x  = symf(g_x);
    float*  hb = symf(g_h);
    float*  tb = symf(g_t);
    float*  rb = symf(g_r);
    float*  vb = symf(g_v);
    float2* rsp;
    { void* p = nullptr; cudaGetSymbolAddress(&p, g_rowstats); rsp = (float2*)p; }

    cudaFuncSetAttribute(gemm3_kernel,  cudaFuncAttributeMaxDynamicSharedMemorySize, GEMM_SMEM);
    cudaFuncSetAttribute(gemm3p_kernel, cudaFuncAttributeMaxDynamicSharedMemorySize, GEMM_SMEM);
    cudaFuncSetAttribute(attn11_kernel<0>, cudaFuncAttributeMaxDynamicSharedMemorySize, ATTN_SMEM);
    cudaFuncSetAttribute(attn11_kernel<1>, cudaFuncAttributeMaxDynamicSharedMemorySize, ATTN_SMEM);

    dim3 ggrid(BN / 32, 2);
    dim3 pgrid(BN / 32, 2, 2);
    dim3 agrid(NN / 32, HH / 2, BB);

    rowstats_kernel<<<BN / 8, 256>>>(md, rsp);
    enc_kernel<<<BN, HID>>>(inputs, en_W, en_b, en);

    // ---- stage 1 (input en, masked mhpa) ----
    gemm3p_kernel<<<pgrid, 256, GEMM_SMEM>>>(en, down_w, vb, w1_W, w1_b, rb);
    attn11_kernel<1><<<agrid, 256, ATTN_SMEM>>>(md, vb, down_r, rsp, hb);
    gemm3_kernel<<<ggrid, 256, GEMM_SMEM>>>(hb, mlp1_W1, mlp1_b1, nullptr, tb, 1);
    gemm3_kernel<<<ggrid, 256, GEMM_SMEM>>>(tb, mlp1_W2, mlp1_b2, rb, x, 1);

    // ---- 4 unmasked blocks ----
    for (int i = 0; i < 4; ++i) {
        gemm3p_kernel<<<pgrid, 256, GEMM_SMEM>>>(x, pa_w + (size_t)i * HH * HID * VD, vb,
            wi_W + (size_t)i * HID * HID, wi_b + (size_t)i * HID, rb);
        attn11_kernel<0><<<agrid, 256, ATTN_SMEM>>>(md, vb, pa_r + (size_t)i * HH, rsp, hb);
        gemm3_kernel<<<ggrid, 256, GEMM_SMEM>>>(hb, blk_W1 + (size_t)i * HID * HID, blk_b1 + (size_t)i * HID, nullptr, tb, 1);
        gemm3_kernel<<<ggrid, 256, GEMM_SMEM>>>(tb, blk_W2 + (size_t)i * HID * HID, blk_b2 + (size_t)i * HID, rb, x, 1);
    }

    // ---- stage 2 (masked mhpa) ----
    gemm3p_kernel<<<pgrid, 256, GEMM_SMEM>>>(x, up_w, vb, w2_W, w2_b, rb);
    attn11_kernel<1><<<agrid, 256, ATTN_SMEM>>>(md, vb, up_r, rsp, hb);
    gemm3_kernel<<<ggrid, 256, GEMM_SMEM>>>(hb, mlp2_W1, mlp2_b1, nullptr, tb, 1);
    gemm3_kernel<<<ggrid, 256, GEMM_SMEM>>>(tb, mlp2_W2, mlp2_b2, rb, x, 1);   // x = de

    // ---- decoder ----
    gemm3_kernel<<<ggrid, 256, GEMM_SMEM>>>(x, de_W1, de_b1, nullptr, tb, 1);
    final_kernel<<<BN / 8, 256>>>(tb, de_W2, de_b2, outp);
}

// round 13
// speedup vs baseline: 1.0216x; 1.0216x over previous
#include <cuda_runtime.h>
#include <math.h>

#define FULLMASK 0xffffffffu

#define BB   2
#define NN   2048
#define HH   8
#define HID  128
#define VD   16
#define BN   (BB * NN)
// locality=5 -> pos=0.05*2047=102.35 -> need 103rd smallest (0-indexed 102)
#define KTH  103

// GEMM smem: Ws [128][64] f32 (32KB) + As [32][128] f32 (16KB) = 48KB
#define GEMM_SMEM (32768 + 16384)
// Attention smem: head-paired v chunk: 512 rows x 18 ull (144B) = 73.7KB -> 2 CTAs/SM
#define VCHUNK 512
#define VSTRU  18
#define ATTN_SMEM (VCHUNK * VSTRU * 8)

typedef unsigned long long ull;

// ---------------- scratch (device globals; no allocation) ----------------
__device__ float  g_en[BN * HID];
__device__ float  g_x [BN * HID];
__device__ float  g_h [BN * HID];
__device__ float  g_t [BN * HID];
__device__ float  g_r [BN * HID];
__device__ float  g_v [BN * HID];
__device__ float2 g_rowstats[BN];

// ---------------- f32x2 packed helpers ----------------
__device__ __forceinline__ ull pack2(float x, float y) {
    ull r;
    asm("mov.b64 %0, {%1, %2};" : "=l"(r) : "r"(__float_as_uint(x)), "r"(__float_as_uint(y)));
    return r;
}
__device__ __forceinline__ void unpack2(ull u, float& x, float& y) {
    unsigned a, b;
    asm("mov.b64 {%0, %1}, %2;" : "=r"(a), "=r"(b) : "l"(u));
    x = __uint_as_float(a); y = __uint_as_float(b);
}
__device__ __forceinline__ ull fma2(ull a, ull b, ull c) {
    ull d;
    asm("fma.rn.f32x2 %0, %1, %2, %3;" : "=l"(d) : "l"(a), "l"(b), "l"(c));
    return d;
}
__device__ __forceinline__ ull add2(ull a, ull b) {
    ull d;
    asm("add.rn.f32x2 %0, %1, %2;" : "=l"(d) : "l"(a), "l"(b));
    return d;
}
__device__ __forceinline__ float ex2f(float x) {
    float r;
    asm("ex2.approx.f32 %0, %1;" : "=f"(r) : "f"(x));
    return r;
}

__device__ __forceinline__ float gelu_f(float x) {
    // exact (erf) gelu, matching jax.nn.gelu(approximate=False)
    return 0.5f * x * (1.0f + erff(x * 0.70710678118654752f));
}

// ---------------- per-row order statistics of m_dist ----------------
__global__ void rowstats_kernel(const float* __restrict__ md, float2* __restrict__ rs) {
    int warp = threadIdx.x >> 5, lane = threadIdx.x & 31;
    int row = blockIdx.x * 8 + warp;
    const float* p = md + (size_t)row * NN + lane;
    unsigned mu[64];
    float mn = 1e30f;
#pragma unroll
    for (int i = 0; i < 64; ++i) {
        float x = p[i * 32];
        mn = fminf(mn, x);
        mu[i] = __float_as_uint(x);
    }
#pragma unroll
    for (int off = 16; off; off >>= 1)
        mn = fminf(mn, __shfl_xor_sync(FULLMASK, mn, off));

    unsigned lo = 0u, hi = 0x3F800000u;  // bit patterns of [0,1)
    while (hi - lo > 1u) {
        unsigned mid = (lo + hi) >> 1;
        int c = 0;
#pragma unroll
        for (int i = 0; i < 64; ++i) c += (mu[i] <= mid) ? 1 : 0;
        c = __reduce_add_sync(FULLMASK, c);
        if (c >= KTH) hi = mid; else lo = mid;
    }
    if (lane == 0) rs[row] = make_float2(mn, __uint_as_float(hi));
}

// ---------------- encoder: gelu(inputs @ en_W + en_b), K=3 ----------------
__global__ void enc_kernel(const float* __restrict__ inp, const float* __restrict__ W,
                           const float* __restrict__ bvec, float* __restrict__ out) {
    int token = blockIdx.x, c = threadIdx.x;
    float x0 = inp[token * 3 + 0];
    float x1 = inp[token * 3 + 1];
    float x2 = inp[token * 3 + 2];
    float s = bvec[c];
    s = fmaf(x0, W[c], s);
    s = fmaf(x1, W[HID + c], s);
    s = fmaf(x2, W[2 * HID + c], s);
    out[(size_t)token * HID + c] = gelu_f(s);
}

// ---------------- GEMM body: 32 rows x 64 cols per CTA ----------------
// vproj: W is head-major (H, HID, VD); logical col c maps to
// W[(c>>4)*HID*VD + k*VD + (c&15)] — 4 consecutive cols stay contiguous.
__device__ __forceinline__ void gemm3_body(
    const float* __restrict__ A, const float* __restrict__ W,
    const float* __restrict__ bias, const float* __restrict__ res,
    float* __restrict__ out, int act, int vproj, float* sm)
{
    float* Ws = sm;              // [128][64]
    float* As = sm + 128 * 64;   // [32][128]

    int tid = threadIdx.x, lane = tid & 31, warp = tid >> 5;
    int row0 = blockIdx.x * 32;
    int cbase = blockIdx.y * 64;

    if (vproj) {
#pragma unroll
        for (int idx = tid; idx < 128 * 16; idx += 256) {
            int k = idx >> 4, q = idx & 15;
            int c0 = cbase + q * 4;
            const float* src = W + (size_t)(c0 >> 4) * (HID * VD) + k * VD + (c0 & 15);
            *(float4*)(Ws + k * 64 + q * 4) = *(const float4*)src;
        }
    } else {
#pragma unroll
        for (int idx = tid; idx < 128 * 16; idx += 256) {
            int k = idx >> 4, q = idx & 15;
            *(float4*)(Ws + k * 64 + q * 4) = *(const float4*)(W + (size_t)k * HID + cbase + q * 4);
        }
    }
#pragma unroll
    for (int idx = tid; idx < 32 * 32; idx += 256) {
        int r = idx >> 5, q = idx & 31;
        *(float4*)(As + r * HID + q * 4) = *(const float4*)(A + (size_t)(row0 + r) * HID + q * 4);
    }
    __syncthreads();

    ull acc[4] = {0ull, 0ull, 0ull, 0ull};
    const ull* Wu = (const ull*)Ws;          // [k][32]
    const float* a0 = As + warp * 4 * HID;

#pragma unroll 8
    for (int k = 0; k < HID; ++k) {
        ull wp = Wu[k * 32 + lane];
        float x0 = a0[0 * HID + k];
        float x1 = a0[1 * HID + k];
        float x2 = a0[2 * HID + k];
        float x3 = a0[3 * HID + k];
        acc[0] = fma2(pack2(x0, x0), wp, acc[0]);
        acc[1] = fma2(pack2(x1, x1), wp, acc[1]);
        acc[2] = fma2(pack2(x2, x2), wp, acc[2]);
        acc[3] = fma2(pack2(x3, x3), wp, acc[3]);
    }

    float b0 = 0.f, b1 = 0.f;
    if (bias) {
        float2 bv = *(const float2*)(bias + cbase + 2 * lane);
        b0 = bv.x; b1 = bv.y;
    }
#pragma unroll
    for (int i = 0; i < 4; ++i) {
        int row = row0 + warp * 4 + i;
        float o0, o1;
        unpack2(acc[i], o0, o1);
        o0 += b0; o1 += b1;
        if (res) {
            float2 rv = *(const float2*)(res + (size_t)row * HID + cbase + 2 * lane);
            o0 += rv.x; o1 += rv.y;
        }
        if (act) { o0 = gelu_f(o0); o1 = gelu_f(o1); }
        *(float2*)(out + (size_t)row * HID + cbase + 2 * lane) = make_float2(o0, o1);
    }
}

__global__ void __launch_bounds__(256) gemm3_kernel(
    const float* __restrict__ A, const float* __restrict__ W,
    const float* __restrict__ bias, const float* __restrict__ res,
    float* __restrict__ out, int act)
{
    extern __shared__ float sm[];
    gemm3_body(A, W, bias, res, out, act, 0, sm);
}

// paired GEMM on the same A. z=0: v-proj from head-major Whead (no bias).
// z=1: skip-proj out1 = A@W1 + b1.
__global__ void __launch_bounds__(256) gemm3p_kernel(
    const float* __restrict__ A,
    const float* __restrict__ Whead, float* __restrict__ out0,
    const float* __restrict__ W1, const float* __restrict__ b1,
    float* __restrict__ out1)
{
    extern __shared__ float sm[];
    if (blockIdx.z == 0) gemm3_body(A, Whead, nullptr, nullptr, out0, 0, 1, sm);
    else                 gemm3_body(A, W1,    b1,      nullptr, out1, 0, 0, sm);
}

// ---------------- fused percentile-softmax attention + gelu (head-paired) --
// One CTA per (16 rows, head-PAIR hp, batch b). Both heads share the same m
// row and mask predicate (sd = m*r^2 monotone per head): each m LDG, FSETP,
// and loop step serves 2 heads. v interleaved in smem as
// ull(v_hA[j][d], v_hB[j][d]); each fma2 computes both heads for one dim.
// 2 ROWS/WARP (vs attn11's 4): acc[2][8] ull = 32 regs -> no spill (~90 regs).
// Lane = (jl 0..15, dh 0..1 dim half). Stride 18 ull rows: quarter-warp
// LDS.128 bank starts {0,4,..,28} conflict-free. 73.7KB smem -> 2 CTAs/SM.
// Depth-2 m prefetch ring (~300cyc step > 262cyc L2).
template <int MASKED>
__global__ void __launch_bounds__(256, 2) attn12_kernel(
    const float* __restrict__ md, const float* __restrict__ v,
    const float* __restrict__ rvec, const float2* __restrict__ rs,
    float* __restrict__ out)
{
    extern __shared__ ull vsu[];   // [VCHUNK][18]
    int b = blockIdx.z, hp = blockIdx.y;
    int hA = 2 * hp, hB = 2 * hp + 1;
    float rA = rvec[hA], rB = rvec[hB];
    float r2A = rA * rA, r2B = rB * rB;
    const float L2E = 1.4426950408889634f;
    float nr2lA = -r2A * L2E, nr2lB = -r2B * L2E;

    int tid = threadIdx.x;
    int lane = tid & 31, warp = tid >> 5;
    int jl = lane & 15, dh = lane >> 4;
    int i0 = blockIdx.x * 16 + warp * 2;

    float msA[2], msB[2], s102[2];
    ull wsum2[2];                   // packed (wsumA, wsumB) per row
    ull acc[2][8];
#pragma unroll
    for (int g = 0; g < 2; ++g) {
        float2 st = rs[b * NN + i0 + g];
        msA[g] = (st.x * r2A) * L2E;  // st.x*r2 == min_j(sd) exactly (monotone)
        msB[g] = (st.x * r2B) * L2E;
        s102[g] = st.y;
        wsum2[g] = 0ull;
#pragma unroll
        for (int d = 0; d < 8; ++d) acc[g][d] = 0ull;
    }

    const float* mrow = md + ((size_t)b * NN + i0) * NN + jl;

    // prime depth-2 m prefetch ring over 16-wide steps (0..127)
    float mr[2][2];
#pragma unroll
    for (int d = 0; d < 2; ++d)
#pragma unroll
        for (int g = 0; g < 2; ++g) mr[g][d] = mrow[(size_t)g * NN + 16 * d];

    const float* vgA = v + (size_t)b * NN * HID + hA * VD;
    const float* vgB = v + (size_t)b * NN * HID + hB * VD;

    for (int c = 0; c < NN / VCHUNK; ++c) {
        __syncthreads();
        // stage interleaved v chunk: vsu[j][d] = (vA[j][d], vB[j][d])
        for (int idx = tid; idx < VCHUNK * 8; idx += 256) {
            int jj = idx >> 3, q = (idx & 7) << 1;   // dims q, q+1
            size_t go = (size_t)(c * VCHUNK + jj) * HID + q;
            float2 a = *(const float2*)(vgA + go);
            float2 bb = *(const float2*)(vgB + go);
            ull* dst = vsu + jj * VSTRU + q;
            dst[0] = pack2(a.x, bb.x);
            dst[1] = pack2(a.y, bb.y);
        }
        __syncthreads();

#pragma unroll 4
        for (int t = 0; t < VCHUNK / 16; ++t) {
            int gt = c * (VCHUNK / 16) + t;
            int slot = gt & 1;

            // 8 dims x 2 heads = 8 ull = 4 aligned LDS.128
            const ulonglong2* vrow = (const ulonglong2*)(vsu + (16 * t + jl) * VSTRU + dh * 8);
            ulonglong2 p0 = vrow[0], p1 = vrow[1], p2 = vrow[2], p3 = vrow[3];
            ull v0 = p0.x, v1 = p0.y, v2 = p1.x, v3 = p1.y;
            ull v4 = p2.x, v5 = p2.y, v6 = p3.x, v7 = p3.y;

            float m0 = mr[0][slot], m1 = mr[1][slot];

            // prefetch m for step gt+2 (clamped; tail prefetches unused)
            int tp = gt + 2; if (tp > NN / 16 - 1) tp = NN / 16 - 1;
            mr[0][slot] = mrow[0 * (size_t)NN + 16 * tp];
            mr[1][slot] = mrow[1 * (size_t)NN + 16 * tp];

            ull wp0, wp1;
            {
                float eA = ex2f(fmaf(m0, nr2lA, msA[0]));
                float eB = ex2f(fmaf(m0, nr2lB, msB[0]));
                ull w = pack2(eA, eB);
                wp0 = MASKED ? ((m0 <= s102[0]) ? w : 0ull) : w;
            }
            {
                float eA = ex2f(fmaf(m1, nr2lA, msA[1]));
                float eB = ex2f(fmaf(m1, nr2lB, msB[1]));
                ull w = pack2(eA, eB);
                wp1 = MASKED ? ((m1 <= s102[1]) ? w : 0ull) : w;
            }
            wsum2[0] = add2(wsum2[0], wp0);
            wsum2[1] = add2(wsum2[1], wp1);

            acc[0][0] = fma2(wp0, v0, acc[0][0]);  acc[0][1] = fma2(wp0, v1, acc[0][1]);
            acc[0][2] = fma2(wp0, v2, acc[0][2]);  acc[0][3] = fma2(wp0, v3, acc[0][3]);
            acc[0][4] = fma2(wp0, v4, acc[0][4]);  acc[0][5] = fma2(wp0, v5, acc[0][5]);
            acc[0][6] = fma2(wp0, v6, acc[0][6]);  acc[0][7] = fma2(wp0, v7, acc[0][7]);

            acc[1][0] = fma2(wp1, v0, acc[1][0]);  acc[1][1] = fma2(wp1, v1, acc[1][1]);
            acc[1][2] = fma2(wp1, v2, acc[1][2]);  acc[1][3] = fma2(wp1, v3, acc[1][3]);
            acc[1][4] = fma2(wp1, v4, acc[1][4]);  acc[1][5] = fma2(wp1, v5, acc[1][5]);
            acc[1][6] = fma2(wp1, v6, acc[1][6]);  acc[1][7] = fma2(wp1, v7, acc[1][7]);
        }
    }

    // butterfly reduce across the 16 jl slots (xor bits 0..3 stays in dh half)
#pragma unroll
    for (int off = 8; off; off >>= 1) {
#pragma unroll
        for (int g = 0; g < 2; ++g) {
            ull o = __shfl_xor_sync(FULLMASK, wsum2[g], off);
            wsum2[g] = add2(wsum2[g], o);
#pragma unroll
            for (int d = 0; d < 8; ++d) {
                ull a = __shfl_xor_sync(FULLMASK, acc[g][d], off);
                acc[g][d] = add2(acc[g][d], a);
            }
        }
    }

    if (jl < 2) {
        int g = jl;
        float wA, wB;
        unpack2(wsum2[g], wA, wB);
        float invA = 1.0f / wA, invB = 1.0f / wB;
        float oA[8], oB[8];
#pragma unroll
        for (int d = 0; d < 8; ++d) {
            float a, bb;
            unpack2(acc[g][d], a, bb);
            oA[d] = gelu_f(a * invA);
            oB[d] = gelu_f(bb * invB);
        }
        float* base = out + (size_t)(b * NN + i0 + g) * HID;
        float* dA = base + hA * VD + dh * 8;
        float* dB = base + hB * VD + dh * 8;
        *(float4*)(dA + 0) = make_float4(oA[0], oA[1], oA[2], oA[3]);
        *(float4*)(dA + 4) = make_float4(oA[4], oA[5], oA[6], oA[7]);
        *(float4*)(dB + 0) = make_float4(oB[0], oB[1], oB[2], oB[3]);
        *(float4*)(dB + 4) = make_float4(oB[4], oB[5], oB[6], oB[7]);
    }
}

// ---------------- final 128 -> 1 projection ----------------
__global__ void final_kernel(const float* __restrict__ t, const float* __restrict__ W,
                             const float* __restrict__ bvec, float* __restrict__ out) {
    int warp = threadIdx.x >> 5, lane = threadIdx.x & 31;
    int token = blockIdx.x * 8 + warp;
    const float* p = t + (size_t)token * HID;
    float s = 0.f;
#pragma unroll
    for (int i = 0; i < 4; ++i) s = fmaf(p[lane + 32 * i], W[lane + 32 * i], s);
#pragma unroll
    for (int off = 16; off; off >>= 1) s += __shfl_xor_sync(FULLMASK, s, off);
    if (lane == 0) out[token] = s + bvec[0];
}

// ---------------- orchestration ----------------
static float* symf(const void* sym) {
    void* p = nullptr;
    cudaGetSymbolAddress(&p, sym);
    return (float*)p;
}

extern "C" void kernel_launch(void* const* d_in, const int* in_sizes, int n_in,
                              void* d_out, int out_size) {
    const float* md      = (const float*)d_in[0];
    const float* inputs  = (const float*)d_in[1];
    const float* en_W    = (const float*)d_in[2];
    const float* en_b    = (const float*)d_in[3];
    const float* down_r  = (const float*)d_in[4];
    const float* down_w  = (const float*)d_in[5];
    const float* mlp1_W1 = (const float*)d_in[6];
    const float* mlp1_b1 = (const float*)d_in[7];
    const float* mlp1_W2 = (const float*)d_in[8];
    const float* mlp1_b2 = (const float*)d_in[9];
    const float* w1_W    = (const float*)d_in[10];
    const float* w1_b    = (const float*)d_in[11];
    const float* pa_r    = (const float*)d_in[12];
    const float* pa_w    = (const float*)d_in[13];
    const float* blk_W1  = (const float*)d_in[14];
    const float* blk_b1  = (const float*)d_in[15];
    const float* blk_W2  = (const float*)d_in[16];
    const float* blk_b2  = (const float*)d_in[17];
    const float* wi_W    = (const float*)d_in[18];
    const float* wi_b    = (const float*)d_in[19];
    const float* up_r    = (const float*)d_in[20];
    const float* up_w    = (const float*)d_in[21];
    const float* mlp2_W1 = (const float*)d_in[22];
    const float* mlp2_b1 = (const float*)d_in[23];
    const float* mlp2_W2 = (const float*)d_in[24];
    const float* mlp2_b2 = (const float*)d_in[25];
    const float* w2_W    = (const float*)d_in[26];
    const float* w2_b    = (const float*)d_in[27];
    const float* de_W1   = (const float*)d_in[28];
    const float* de_b1   = (const float*)d_in[29];
    const float* de_W2   = (const float*)d_in[30];
    const float* de_b2   = (const float*)d_in[31];
    float* outp = (float*)d_out;

    float*  en = symf(g_en);
    float*  x  = symf(g_x);
    float*  hb = symf(g_h);
    float*  tb = symf(g_t);
    float*  rb = symf(g_r);
    float*  vb = symf(g_v);
    float2* rsp;
    { void* p = nullptr; cudaGetSymbolAddress(&p, g_rowstats); rsp = (float2*)p; }

    cudaFuncSetAttribute(gemm3_kernel,  cudaFuncAttributeMaxDynamicSharedMemorySize, GEMM_SMEM);
    cudaFuncSetAttribute(gemm3p_kernel, cudaFuncAttributeMaxDynamicSharedMemorySize, GEMM_SMEM);
    cudaFuncSetAttribute(attn12_kernel<0>, cudaFuncAttributeMaxDynamicSharedMemorySize, ATTN_SMEM);
    cudaFuncSetAttribute(attn12_kernel<1>, cudaFuncAttributeMaxDynamicSharedMemorySize, ATTN_SMEM);

    dim3 ggrid(BN / 32, 2);
    dim3 pgrid(BN / 32, 2, 2);
    dim3 agrid(NN / 16, HH / 2, BB);

    rowstats_kernel<<<BN / 8, 256>>>(md, rsp);
    enc_kernel<<<BN, HID>>>(inputs, en_W, en_b, en);

    // ---- stage 1 (input en, masked mhpa) ----
    gemm3p_kernel<<<pgrid, 256, GEMM_SMEM>>>(en, down_w, vb, w1_W, w1_b, rb);
    attn12_kernel<1><<<agrid, 256, ATTN_SMEM>>>(md, vb, down_r, rsp, hb);
    gemm3_kernel<<<ggrid, 256, GEMM_SMEM>>>(hb, mlp1_W1, mlp1_b1, nullptr, tb, 1);
    gemm3_kernel<<<ggrid, 256, GEMM_SMEM>>>(tb, mlp1_W2, mlp1_b2, rb, x, 1);

    // ---- 4 unmasked blocks ----
    for (int i = 0; i < 4; ++i) {
        gemm3p_kernel<<<pgrid, 256, GEMM_SMEM>>>(x, pa_w + (size_t)i * HH * HID * VD, vb,
            wi_W + (size_t)i * HID * HID, wi_b + (size_t)i * HID, rb);
        attn12_kernel<0><<<agrid, 256, ATTN_SMEM>>>(md, vb, pa_r + (size_t)i * HH, rsp, hb);
        gemm3_kernel<<<ggrid, 256, GEMM_SMEM>>>(hb, blk_W1 + (size_t)i * HID * HID, blk_b1 + (size_t)i * HID, nullptr, tb, 1);
        gemm3_kernel<<<ggrid, 256, GEMM_SMEM>>>(tb, blk_W2 + (size_t)i * HID * HID, blk_b2 + (size_t)i * HID, rb, x, 1);
    }

    // ---- stage 2 (masked mhpa) ----
    gemm3p_kernel<<<pgrid, 256, GEMM_SMEM>>>(x, up_w, vb, w2_W, w2_b, rb);
    attn12_kernel<1><<<agrid, 256, ATTN_SMEM>>>(md, vb, up_r, rsp, hb);
    gemm3_kernel<<<ggrid, 256, GEMM_SMEM>>>(hb, mlp2_W1, mlp2_b1, nullptr, tb, 1);
    gemm3_kernel<<<ggrid, 256, GEMM_SMEM>>>(tb, mlp2_W2, mlp2_b2, rb, x, 1);   // x = de

    // ---- decoder ----
    gemm3_kernel<<<ggrid, 256, GEMM_SMEM>>>(x, de_W1, de_b1, nullptr, tb, 1);
    final_kernel<<<BN / 8, 256>>>(tb, de_W2, de_b2, outp);
}

// round 14
// speedup vs baseline: 1.2924x; 1.2650x over previous
#include <cuda_runtime.h>
#include <math.h>

#define FULLMASK 0xffffffffu

#define BB   2
#define NN   2048
#define HH   8
#define HID  128
#define VD   16
#define BN   (BB * NN)
// locality=5 -> pos=0.05*2047=102.35 -> need 103rd smallest (0-indexed 102)
#define KTH  103

// GEMM smem: Ws [128][64] f32 (32KB) + As [32][128] f32 (16KB) = 48KB
#define GEMM_SMEM (32768 + 16384)
// Attention smem: half of v (1024 rows x stride-20 f32) = 80KB -> 2 CTAs/SM
#define VCHUNK 1024
#define VSTR   20
#define ATTN_SMEM (VCHUNK * VSTR * 4)

typedef unsigned long long ull;

// ---------------- scratch (device globals; no allocation) ----------------
__device__ float  g_en[BN * HID];
__device__ float  g_x [BN * HID];
__device__ float  g_h [BN * HID];
__device__ float  g_t [BN * HID];
__device__ float  g_r [BN * HID];
__device__ float  g_v [BN * HID];
__device__ float2 g_rowstats[BN];
__device__ int    g_sidx[BN * 128];
__device__ float  g_sm  [BN * 128];

// ---------------- f32x2 packed helpers ----------------
__device__ __forceinline__ ull pack2(float x, float y) {
    ull r;
    asm("mov.b64 %0, {%1, %2};" : "=l"(r) : "r"(__float_as_uint(x)), "r"(__float_as_uint(y)));
    return r;
}
__device__ __forceinline__ void unpack2(ull u, float& x, float& y) {
    unsigned a, b;
    asm("mov.b64 {%0, %1}, %2;" : "=r"(a), "=r"(b) : "l"(u));
    x = __uint_as_float(a); y = __uint_as_float(b);
}
__device__ __forceinline__ ull fma2(ull a, ull b, ull c) {
    ull d;
    asm("fma.rn.f32x2 %0, %1, %2, %3;" : "=l"(d) : "l"(a), "l"(b), "l"(c));
    return d;
}
__device__ __forceinline__ ull add2(ull a, ull b) {
    ull d;
    asm("add.rn.f32x2 %0, %1, %2;" : "=l"(d) : "l"(a), "l"(b));
    return d;
}
__device__ __forceinline__ float ex2f(float x) {
    float r;
    asm("ex2.approx.f32 %0, %1;" : "=f"(r) : "f"(x));
    return r;
}

__device__ __forceinline__ float gelu_f(float x) {
    // exact (erf) gelu, matching jax.nn.gelu(approximate=False)
    return 0.5f * x * (1.0f + erff(x * 0.70710678118654752f));
}

// ---------------- per-row order statistics of m_dist ----------------
__global__ void rowstats_kernel(const float* __restrict__ md, float2* __restrict__ rs) {
    int warp = threadIdx.x >> 5, lane = threadIdx.x & 31;
    int row = blockIdx.x * 8 + warp;
    const float* p = md + (size_t)row * NN + lane;
    unsigned mu[64];
    float mn = 1e30f;
#pragma unroll
    for (int i = 0; i < 64; ++i) {
        float x = p[i * 32];
        mn = fminf(mn, x);
        mu[i] = __float_as_uint(x);
    }
#pragma unroll
    for (int off = 16; off; off >>= 1)
        mn = fminf(mn, __shfl_xor_sync(FULLMASK, mn, off));

    unsigned lo = 0u, hi = 0x3F800000u;  // bit patterns of [0,1)
    while (hi - lo > 1u) {
        unsigned mid = (lo + hi) >> 1;
        int c = 0;
#pragma unroll
        for (int i = 0; i < 64; ++i) c += (mu[i] <= mid) ? 1 : 0;
        c = __reduce_add_sync(FULLMASK, c);
        if (c >= KTH) hi = mid; else lo = mid;
    }
    if (lane == 0) rs[row] = make_float2(mn, __uint_as_float(hi));
}

// ---------------- masked-set compaction: (j, m) pairs with m <= s102 -------
// One warp per row. Exactly KTH entries (continuous uniforms: no ties);
// padded to 128 with m = 1e30 (weight underflows to exactly 0).
__global__ void sparse_idx_kernel(const float* __restrict__ md,
                                  const float2* __restrict__ rs,
                                  int* __restrict__ sidx, float* __restrict__ smv) {
    int warp = threadIdx.x >> 5, lane = threadIdx.x & 31;
    int row = blockIdx.x * 8 + warp;
    float thr = rs[row].y;
    const float* p = md + (size_t)row * NN;
    int base = 0;
#pragma unroll 4
    for (int t = 0; t < 64; ++t) {
        int j = t * 32 + lane;
        float m = p[j];
        bool sel = (m <= thr);
        unsigned mask = __ballot_sync(FULLMASK, sel);
        if (sel) {
            int pos = base + __popc(mask & ((1u << lane) - 1u));
            sidx[(size_t)row * 128 + pos] = j;
            smv [(size_t)row * 128 + pos] = m;
        }
        base += __popc(mask);
    }
    for (int k = base + lane; k < 128; k += 32) {
        sidx[(size_t)row * 128 + k] = 0;
        smv [(size_t)row * 128 + k] = 1e30f;
    }
}

// ---------------- encoder: gelu(inputs @ en_W + en_b), K=3 ----------------
__global__ void enc_kernel(const float* __restrict__ inp, const float* __restrict__ W,
                           const float* __restrict__ bvec, float* __restrict__ out) {
    int token = blockIdx.x, c = threadIdx.x;
    float x0 = inp[token * 3 + 0];
    float x1 = inp[token * 3 + 1];
    float x2 = inp[token * 3 + 2];
    float s = bvec[c];
    s = fmaf(x0, W[c], s);
    s = fmaf(x1, W[HID + c], s);
    s = fmaf(x2, W[2 * HID + c], s);
    out[(size_t)token * HID + c] = gelu_f(s);
}

// ---------------- GEMM body: 32 rows x 64 cols per CTA ----------------
// vproj: W is head-major (H, HID, VD); logical col c maps to
// W[(c>>4)*HID*VD + k*VD + (c&15)] — 4 consecutive cols stay contiguous.
__device__ __forceinline__ void gemm3_body(
    const float* __restrict__ A, const float* __restrict__ W,
    const float* __restrict__ bias, const float* __restrict__ res,
    float* __restrict__ out, int act, int vproj, float* sm)
{
    float* Ws = sm;              // [128][64]
    float* As = sm + 128 * 64;   // [32][128]

    int tid = threadIdx.x, lane = tid & 31, warp = tid >> 5;
    int row0 = blockIdx.x * 32;
    int cbase = blockIdx.y * 64;

    if (vproj) {
#pragma unroll
        for (int idx = tid; idx < 128 * 16; idx += 256) {
            int k = idx >> 4, q = idx & 15;
            int c0 = cbase + q * 4;
            const float* src = W + (size_t)(c0 >> 4) * (HID * VD) + k * VD + (c0 & 15);
            *(float4*)(Ws + k * 64 + q * 4) = *(const float4*)src;
        }
    } else {
#pragma unroll
        for (int idx = tid; idx < 128 * 16; idx += 256) {
            int k = idx >> 4, q = idx & 15;
            *(float4*)(Ws + k * 64 + q * 4) = *(const float4*)(W + (size_t)k * HID + cbase + q * 4);
        }
    }
#pragma unroll
    for (int idx = tid; idx < 32 * 32; idx += 256) {
        int r = idx >> 5, q = idx & 31;
        *(float4*)(As + r * HID + q * 4) = *(const float4*)(A + (size_t)(row0 + r) * HID + q * 4);
    }
    __syncthreads();

    ull acc[4] = {0ull, 0ull, 0ull, 0ull};
    const ull* Wu = (const ull*)Ws;          // [k][32]
    const float* a0 = As + warp * 4 * HID;

#pragma unroll 8
    for (int k = 0; k < HID; ++k) {
        ull wp = Wu[k * 32 + lane];
        float x0 = a0[0 * HID + k];
        float x1 = a0[1 * HID + k];
        float x2 = a0[2 * HID + k];
        float x3 = a0[3 * HID + k];
        acc[0] = fma2(pack2(x0, x0), wp, acc[0]);
        acc[1] = fma2(pack2(x1, x1), wp, acc[1]);
        acc[2] = fma2(pack2(x2, x2), wp, acc[2]);
        acc[3] = fma2(pack2(x3, x3), wp, acc[3]);
    }

    float b0 = 0.f, b1 = 0.f;
    if (bias) {
        float2 bv = *(const float2*)(bias + cbase + 2 * lane);
        b0 = bv.x; b1 = bv.y;
    }
#pragma unroll
    for (int i = 0; i < 4; ++i) {
        int row = row0 + warp * 4 + i;
        float o0, o1;
        unpack2(acc[i], o0, o1);
        o0 += b0; o1 += b1;
        if (res) {
            float2 rv = *(const float2*)(res + (size_t)row * HID + cbase + 2 * lane);
            o0 += rv.x; o1 += rv.y;
        }
        if (act) { o0 = gelu_f(o0); o1 = gelu_f(o1); }
        *(float2*)(out + (size_t)row * HID + cbase + 2 * lane) = make_float2(o0, o1);
    }
}

__global__ void __launch_bounds__(256) gemm3_kernel(
    const float* __restrict__ A, const float* __restrict__ W,
    const float* __restrict__ bias, const float* __restrict__ res,
    float* __restrict__ out, int act)
{
    extern __shared__ float sm[];
    gemm3_body(A, W, bias, res, out, act, 0, sm);
}

// paired GEMM on the same A. z=0: v-proj from head-major Whead (no bias).
// z=1: skip-proj out1 = A@W1 + b1.
__global__ void __launch_bounds__(256) gemm3p_kernel(
    const float* __restrict__ A,
    const float* __restrict__ Whead, float* __restrict__ out0,
    const float* __restrict__ W1, const float* __restrict__ b1,
    float* __restrict__ out1)
{
    extern __shared__ float sm[];
    if (blockIdx.z == 0) gemm3_body(A, Whead, nullptr, nullptr, out0, 0, 1, sm);
    else                 gemm3_body(A, W1,    b1,      nullptr, out1, 0, 0, sm);
}

// ---------------- dense (unmasked) attention: attn10, proven 112us ---------
__global__ void __launch_bounds__(256, 2) attn_dense_kernel(
    const float* __restrict__ md, const float* __restrict__ v,
    const float* __restrict__ rvec, const float2* __restrict__ rs,
    float* __restrict__ out)
{
    extern __shared__ float vs[];   // [1024][20]
    int b = blockIdx.z, h = blockIdx.y;
    float rr = rvec[h];
    float r2 = rr * rr;
    const float L2E = 1.4426950408889634f;
    float nr2l = -r2 * L2E;

    int tid = threadIdx.x;
    int lane = tid & 31, warp = tid >> 5;
    int jl = lane & 15, dh = lane >> 4;
    int i0 = blockIdx.x * 32 + warp * 4;

    float msdl[4], wsum[4];
    ull acc[4][4];
#pragma unroll
    for (int g = 0; g < 4; ++g) {
        float2 st = rs[b * NN + i0 + g];
        msdl[g] = (st.x * r2) * L2E;  // st.x*r2 == min_j(sd) exactly (monotone)
        wsum[g] = 0.f;
#pragma unroll
        for (int d = 0; d < 4; ++d) acc[g][d] = 0ull;
    }

    const float* mrow = md + ((size_t)b * NN + i0) * NN + jl;

    // prime depth-4 m prefetch ring over global 16-wide steps (0..127)
    float mr[4][4];
#pragma unroll
    for (int d = 0; d < 4; ++d)
#pragma unroll
        for (int g = 0; g < 4; ++g) mr[g][d] = mrow[(size_t)g * NN + 16 * d];

    for (int c = 0; c < NN / VCHUNK; ++c) {
        __syncthreads();
        const float* vg = v + ((size_t)b * NN + c * VCHUNK) * HID + h * VD;
        for (int idx = tid; idx < VCHUNK * 8; idx += 256) {
            int jj = idx >> 3, dd = (idx & 7) << 1;
            float2 val = *(const float2*)(vg + (size_t)jj * HID + dd);
            *(float2*)(vs + jj * VSTR + dd) = val;
        }
        __syncthreads();

#pragma unroll 4
        for (int t = 0; t < VCHUNK / 16; ++t) {
            int gt = c * (VCHUNK / 16) + t;
            int slot = gt & 3;

            const ulonglong2* vrow = (const ulonglong2*)(vs + (16 * t + jl) * VSTR + dh * 8);
            ulonglong2 va = vrow[0], vb2 = vrow[1];
            ull v0 = va.x, v1 = va.y, v2 = vb2.x, v3 = vb2.y;

            float m0 = mr[0][slot], m1 = mr[1][slot], m2 = mr[2][slot], m3 = mr[3][slot];

            int tp = gt + 4; if (tp > NN / 16 - 1) tp = NN / 16 - 1;
            mr[0][slot] = mrow[0 * (size_t)NN + 16 * tp];
            mr[1][slot] = mrow[1 * (size_t)NN + 16 * tp];
            mr[2][slot] = mrow[2 * (size_t)NN + 16 * tp];
            mr[3][slot] = mrow[3 * (size_t)NN + 16 * tp];

            float w0 = ex2f(fmaf(m0, nr2l, msdl[0]));
            float w1 = ex2f(fmaf(m1, nr2l, msdl[1]));
            float w2 = ex2f(fmaf(m2, nr2l, msdl[2]));
            float w3 = ex2f(fmaf(m3, nr2l, msdl[3]));
            wsum[0] += w0;
            wsum[1] += w1;
            wsum[2] += w2;
            wsum[3] += w3;
            ull wp0 = pack2(w0, w0);
            ull wp1 = pack2(w1, w1);
            ull wp2 = pack2(w2, w2);
            ull wp3 = pack2(w3, w3);

            acc[0][0] = fma2(wp0, v0, acc[0][0]);  acc[0][1] = fma2(wp0, v1, acc[0][1]);
            acc[0][2] = fma2(wp0, v2, acc[0][2]);  acc[0][3] = fma2(wp0, v3, acc[0][3]);

            acc[1][0] = fma2(wp1, v0, acc[1][0]);  acc[1][1] = fma2(wp1, v1, acc[1][1]);
            acc[1][2] = fma2(wp1, v2, acc[1][2]);  acc[1][3] = fma2(wp1, v3, acc[1][3]);

            acc[2][0] = fma2(wp2, v0, acc[2][0]);  acc[2][1] = fma2(wp2, v1, acc[2][1]);
            acc[2][2] = fma2(wp2, v2, acc[2][2]);  acc[2][3] = fma2(wp2, v3, acc[2][3]);

            acc[3][0] = fma2(wp3, v0, acc[3][0]);  acc[3][1] = fma2(wp3, v1, acc[3][1]);
            acc[3][2] = fma2(wp3, v2, acc[3][2]);  acc[3][3] = fma2(wp3, v3, acc[3][3]);
        }
    }

#pragma unroll
    for (int off = 8; off; off >>= 1) {
#pragma unroll
        for (int g = 0; g < 4; ++g) {
            wsum[g] += __shfl_xor_sync(FULLMASK, wsum[g], off);
#pragma unroll
            for (int d = 0; d < 4; ++d) {
                ull o = __shfl_xor_sync(FULLMASK, acc[g][d], off);
                acc[g][d] = add2(acc[g][d], o);
            }
        }
    }

    if (jl < 4) {
        int g = jl;
        float inv = 1.0f / wsum[g];
        float o[8];
#pragma unroll
        for (int d = 0; d < 4; ++d) unpack2(acc[g][d], o[2 * d], o[2 * d + 1]);
#pragma unroll
        for (int e = 0; e < 8; ++e) o[e] = gelu_f(o[e] * inv);
        float* dst = out + (size_t)(b * NN + i0 + g) * HID + h * VD + dh * 8;
        *(float4*)(dst + 0) = make_float4(o[0], o[1], o[2], o[3]);
        *(float4*)(dst + 4) = make_float4(o[4], o[5], o[6], o[7]);
    }
}

// ---------------- sparse (masked) attention + gelu -------------------------
// Only the KTH smallest m per row carry nonzero weight; (j,m) pairs are
// precompacted (padded to 128 with m=1e30 -> w=0). One warp per (row,h):
// 4 steps x 32 pairs; v gathered from L2-resident g_v (4x LDG.128 per pair).
__global__ void __launch_bounds__(256) attn_sparse_kernel(
    const float* __restrict__ v, const float* __restrict__ rvec,
    const float2* __restrict__ rs,
    const int* __restrict__ sidx, const float* __restrict__ smv,
    float* __restrict__ out)
{
    int b = blockIdx.z, h = blockIdx.y;
    float rr = rvec[h];
    float r2 = rr * rr;
    const float L2E = 1.4426950408889634f;
    float nr2l = -r2 * L2E;

    int lane = threadIdx.x & 31, warp = threadIdx.x >> 5;
    int i = blockIdx.x * 8 + warp;
    int grow = b * NN + i;

    float msdl = (rs[grow].x * r2) * L2E;
    const int*   ip = sidx + (size_t)grow * 128;
    const float* mp = smv  + (size_t)grow * 128;
    const float* vbase = v + (size_t)b * NN * HID + h * VD;

    ull acc[8];
#pragma unroll
    for (int d = 0; d < 8; ++d) acc[d] = 0ull;
    float wsum = 0.f;

#pragma unroll
    for (int t = 0; t < 4; ++t) {
        int k = t * 32 + lane;
        int idx = ip[k];
        float m = mp[k];
        float w = ex2f(fmaf(m, nr2l, msdl));   // padding: m=1e30 -> w=0
        wsum += w;
        const ulonglong2* vp = (const ulonglong2*)(vbase + (size_t)idx * HID);
        ulonglong2 p0 = vp[0], p1 = vp[1], p2 = vp[2], p3 = vp[3];
        ull wp = pack2(w, w);
        acc[0] = fma2(wp, p0.x, acc[0]);
        acc[1] = fma2(wp, p0.y, acc[1]);
        acc[2] = fma2(wp, p1.x, acc[2]);
        acc[3] = fma2(wp, p1.y, acc[3]);
        acc[4] = fma2(wp, p2.x, acc[4]);
        acc[5] = fma2(wp, p2.y, acc[5]);
        acc[6] = fma2(wp, p3.x, acc[6]);
        acc[7] = fma2(wp, p3.y, acc[7]);
    }

#pragma unroll
    for (int off = 16; off; off >>= 1) {
        wsum += __shfl_xor_sync(FULLMASK, wsum, off);
#pragma unroll
        for (int d = 0; d < 8; ++d) {
            ull o = __shfl_xor_sync(FULLMASK, acc[d], off);
            acc[d] = add2(acc[d], o);
        }
    }

    if (lane == 0) {
        float inv = 1.0f / wsum;
        float o[16];
#pragma unroll
        for (int d = 0; d < 8; ++d) unpack2(acc[d], o[2 * d], o[2 * d + 1]);
#pragma unroll
        for (int e = 0; e < 16; ++e) o[e] = gelu_f(o[e] * inv);
        float* dst = out + (size_t)grow * HID + h * VD;
        *(float4*)(dst + 0)  = make_float4(o[0],  o[1],  o[2],  o[3]);
        *(float4*)(dst + 4)  = make_float4(o[4],  o[5],  o[6],  o[7]);
        *(float4*)(dst + 8)  = make_float4(o[8],  o[9],  o[10], o[11]);
        *(float4*)(dst + 12) = make_float4(o[12], o[13], o[14], o[15]);
    }
}

// ---------------- final 128 -> 1 projection ----------------
__global__ void final_kernel(const float* __restrict__ t, const float* __restrict__ W,
                             const float* __restrict__ bvec, float* __restrict__ out) {
    int warp = threadIdx.x >> 5, lane = threadIdx.x & 31;
    int token = blockIdx.x * 8 + warp;
    const float* p = t + (size_t)token * HID;
    float s = 0.f;
#pragma unroll
    for (int i = 0; i < 4; ++i) s = fmaf(p[lane + 32 * i], W[lane + 32 * i], s);
#pragma unroll
    for (int off = 16; off; off >>= 1) s += __shfl_xor_sync(FULLMASK, s, off);
    if (lane == 0) out[token] = s + bvec[0];
}

// ---------------- orchestration ----------------
static float* symf(const void* sym) {
    void* p = nullptr;
    cudaGetSymbolAddress(&p, sym);
    return (float*)p;
}

extern "C" void kernel_launch(void* const* d_in, const int* in_sizes, int n_in,
                              void* d_out, int out_size) {
    const float* md      = (const float*)d_in[0];
    const float* inputs  = (const float*)d_in[1];
    const float* en_W    = (const float*)d_in[2];
    const float* en_b    = (const float*)d_in[3];
    const float* down_r  = (const float*)d_in[4];
    const float* down_w  = (const float*)d_in[5];
    const float* mlp1_W1 = (const float*)d_in[6];
    const float* mlp1_b1 = (const float*)d_in[7];
    const float* mlp1_W2 = (const float*)d_in[8];
    const float* mlp1_b2 = (const float*)d_in[9];
    const float* w1_W    = (const float*)d_in[10];
    const float* w1_b    = (const float*)d_in[11];
    const float* pa_r    = (const float*)d_in[12];
    const float* pa_w    = (const float*)d_in[13];
    const float* blk_W1  = (const float*)d_in[14];
    const float* blk_b1  = (const float*)d_in[15];
    const float* blk_W2  = (const float*)d_in[16];
    const float* blk_b2  = (const float*)d_in[17];
    const float* wi_W    = (const float*)d_in[18];
    const float* wi_b    = (const float*)d_in[19];
    const float* up_r    = (const float*)d_in[20];
    const float* up_w    = (const float*)d_in[21];
    const float* mlp2_W1 = (const float*)d_in[22];
    const float* mlp2_b1 = (const float*)d_in[23];
    const float* mlp2_W2 = (const float*)d_in[24];
    const float* mlp2_b2 = (const float*)d_in[25];
    const float* w2_W    = (const float*)d_in[26];
    const float* w2_b    = (const float*)d_in[27];
    const float* de_W1   = (const float*)d_in[28];
    const float* de_b1   = (const float*)d_in[29];
    const float* de_W2   = (const float*)d_in[30];
    const float* de_b2   = (const float*)d_in[31];
    float* outp = (float*)d_out;

    float*  en = symf(g_en);
    float*  x  = symf(g_x);
    float*  hb = symf(g_h);
    float*  tb = symf(g_t);
    float*  rb = symf(g_r);
    float*  vb = symf(g_v);
    float2* rsp;
    { void* p = nullptr; cudaGetSymbolAddress(&p, g_rowstats); rsp = (float2*)p; }
    int* sidx;
    { void* p = nullptr; cudaGetSymbolAddress(&p, g_sidx); sidx = (int*)p; }
    float* smv = symf(g_sm);

    cudaFuncSetAttribute(gemm3_kernel,  cudaFuncAttributeMaxDynamicSharedMemorySize, GEMM_SMEM);
    cudaFuncSetAttribute(gemm3p_kernel, cudaFuncAttributeMaxDynamicSharedMemorySize, GEMM_SMEM);
    cudaFuncSetAttribute(attn_dense_kernel, cudaFuncAttributeMaxDynamicSharedMemorySize, ATTN_SMEM);

    dim3 ggrid(BN / 32, 2);
    dim3 pgrid(BN / 32, 2, 2);
    dim3 agrid(NN / 32, HH, BB);
    dim3 sgrid(NN / 8, HH, BB);

    rowstats_kernel<<<BN / 8, 256>>>(md, rsp);
    sparse_idx_kernel<<<BN / 8, 256>>>(md, rsp, sidx, smv);
    enc_kernel<<<BN, HID>>>(inputs, en_W, en_b, en);

    // ---- stage 1 (input en, masked mhpa -> sparse) ----
    gemm3p_kernel<<<pgrid, 256, GEMM_SMEM>>>(en, down_w, vb, w1_W, w1_b, rb);
    attn_sparse_kernel<<<sgrid, 256>>>(vb, down_r, rsp, sidx, smv, hb);
    gemm3_kernel<<<ggrid, 256, GEMM_SMEM>>>(hb, mlp1_W1, mlp1_b1, nullptr, tb, 1);
    gemm3_kernel<<<ggrid, 256, GEMM_SMEM>>>(tb, mlp1_W2, mlp1_b2, rb, x, 1);

    // ---- 4 unmasked blocks (dense attention) ----
    for (int i = 0; i < 4; ++i) {
        gemm3p_kernel<<<pgrid, 256, GEMM_SMEM>>>(x, pa_w + (size_t)i * HH * HID * VD, vb,
            wi_W + (size_t)i * HID * HID, wi_b + (size_t)i * HID, rb);
        attn_dense_kernel<<<agrid, 256, ATTN_SMEM>>>(md, vb, pa_r + (size_t)i * HH, rsp, hb);
        gemm3_kernel<<<ggrid, 256, GEMM_SMEM>>>(hb, blk_W1 + (size_t)i * HID * HID, blk_b1 + (size_t)i * HID, nullptr, tb, 1);
        gemm3_kernel<<<ggrid, 256, GEMM_SMEM>>>(tb, blk_W2 + (size_t)i * HID * HID, blk_b2 + (size_t)i * HID, rb, x, 1);
    }

    // ---- stage 2 (masked mhpa -> sparse) ----
    gemm3p_kernel<<<pgrid, 256, GEMM_SMEM>>>(x, up_w, vb, w2_W, w2_b, rb);
    attn_sparse_kernel<<<sgrid, 256>>>(vb, up_r, rsp, sidx, smv, hb);
    gemm3_kernel<<<ggrid, 256, GEMM_SMEM>>>(hb, mlp2_W1, mlp2_b1, nullptr, tb, 1);
    gemm3_kernel<<<ggrid, 256, GEMM_SMEM>>>(tb, mlp2_W2, mlp2_b2, rb, x, 1);   // x = de

    // ---- decoder ----
    gemm3_kernel<<<ggrid, 256, GEMM_SMEM>>>(x, de_W1, de_b1, nullptr, tb, 1);
    final_kernel<<<BN / 8, 256>>>(tb, de_W2, de_b2, outp);
}

// round 16
// speedup vs baseline: 1.6065x; 1.2431x over previous
#include <cuda_runtime.h>
#include <cuda_fp16.h>
#include <math.h>

#define FULLMASK 0xffffffffu

#define BB   2
#define NN   2048
#define HH   8
#define HID  128
#define VD   16
#define BN   (BB * NN)
#define KTH  103

#define GEMM_SMEM (32768 + 16384)
#define MCH    256
#define MS_STR 264

typedef unsigned long long ull;

__device__ float  g_en[BN * HID];
__device__ float  g_x [BN * HID];
__device__ float  g_h [BN * HID];
__device__ float  g_t [BN * HID];
__device__ float  g_r [BN * HID];
__device__ float  g_v [BN * HID];
__device__ __half g_vh[BN * HID];   // v transposed per head: [b][hd][j] fp16
__device__ float2 g_rowstats[BN];
__device__ int    g_sidx[BN * 128];
__device__ float  g_sm  [BN * 128];

// ---------------- helpers ----------------
__device__ __forceinline__ ull pack2(float x, float y) {
    ull r;
    asm("mov.b64 %0, {%1, %2};" : "=l"(r) : "r"(__float_as_uint(x)), "r"(__float_as_uint(y)));
    return r;
}
__device__ __forceinline__ void unpack2(ull u, float& x, float& y) {
    unsigned a, b;
    asm("mov.b64 {%0, %1}, %2;" : "=r"(a), "=r"(b) : "l"(u));
    x = __uint_as_float(a); y = __uint_as_float(b);
}
__device__ __forceinline__ ull fma2(ull a, ull b, ull c) {
    ull d;
    asm("fma.rn.f32x2 %0, %1, %2, %3;" : "=l"(d) : "l"(a), "l"(b), "l"(c));
    return d;
}
__device__ __forceinline__ ull add2(ull a, ull b) {
    ull d;
    asm("add.rn.f32x2 %0, %1, %2;" : "=l"(d) : "l"(a), "l"(b));
    return d;
}
__device__ __forceinline__ float ex2f(float x) {
    float r;
    asm("ex2.approx.f32 %0, %1;" : "=f"(r) : "f"(x));
    return r;
}
__device__ __forceinline__ float gelu_f(float x) {
    return 0.5f * x * (1.0f + erff(x * 0.70710678118654752f));
}
__device__ __forceinline__ unsigned h2u(__half2 h) {
    unsigned u;
    asm("mov.b32 %0, %1;" : "=r"(u) : "r"(*(unsigned*)&h));
    return u;
}
// mma.sync m16n8k16 row.col f32 += f16*f16 (standard PTX; HMMA on sm_103)
__device__ __forceinline__ void mma16816(float d[4],
    unsigned a0, unsigned a1, unsigned a2, unsigned a3,
    unsigned b0, unsigned b1)
{
    asm volatile(
        "mma.sync.aligned.m16n8k16.row.col.f32.f16.f16.f32 "
        "{%0,%1,%2,%3}, {%4,%5,%6,%7}, {%8,%9}, {%0,%1,%2,%3};"
        : "+f"(d[0]), "+f"(d[1]), "+f"(d[2]), "+f"(d[3])
        : "r"(a0), "r"(a1), "r"(a2), "r"(a3), "r"(b0), "r"(b1));
}

// ---------------- per-row order statistics of m_dist ----------------
__global__ void rowstats_kernel(const float* __restrict__ md, float2* __restrict__ rs) {
    int warp = threadIdx.x >> 5, lane = threadIdx.x & 31;
    int row = blockIdx.x * 8 + warp;
    const float* p = md + (size_t)row * NN + lane;
    unsigned mu[64];
    float mn = 1e30f;
#pragma unroll
    for (int i = 0; i < 64; ++i) {
        float x = p[i * 32];
        mn = fminf(mn, x);
        mu[i] = __float_as_uint(x);
    }
#pragma unroll
    for (int off = 16; off; off >>= 1)
        mn = fminf(mn, __shfl_xor_sync(FULLMASK, mn, off));

    unsigned lo = 0u, hi = 0x3F800000u;
    while (hi - lo > 1u) {
        unsigned mid = (lo + hi) >> 1;
        int c = 0;
#pragma unroll
        for (int i = 0; i < 64; ++i) c += (mu[i] <= mid) ? 1 : 0;
        c = __reduce_add_sync(FULLMASK, c);
        if (c >= KTH) hi = mid; else lo = mid;
    }
    if (lane == 0) rs[row] = make_float2(mn, __uint_as_float(hi));
}

// ---------------- masked-set compaction ----------------
__global__ void sparse_idx_kernel(const float* __restrict__ md,
                                  const float2* __restrict__ rs,
                                  int* __restrict__ sidx, float* __restrict__ smv) {
    int warp = threadIdx.x >> 5, lane = threadIdx.x & 31;
    int row = blockIdx.x * 8 + warp;
    float thr = rs[row].y;
    const float* p = md + (size_t)row * NN;
    int base = 0;
#pragma unroll 4
    for (int t = 0; t < 64; ++t) {
        int j = t * 32 + lane;
        float m = p[j];
        bool sel = (m <= thr);
        unsigned mask = __ballot_sync(FULLMASK, sel);
        if (sel) {
            int pos = base + __popc(mask & ((1u << lane) - 1u));
            sidx[(size_t)row * 128 + pos] = j;
            smv [(size_t)row * 128 + pos] = m;
        }
        base += __popc(mask);
    }
    for (int k = base + lane; k < 128; k += 32) {
        sidx[(size_t)row * 128 + k] = 0;
        smv [(size_t)row * 128 + k] = 1e30f;
    }
}

// ---------------- encoder ----------------
__global__ void enc_kernel(const float* __restrict__ inp, const float* __restrict__ W,
                           const float* __restrict__ bvec, float* __restrict__ out) {
    int token = blockIdx.x, c = threadIdx.x;
    float x0 = inp[token * 3 + 0];
    float x1 = inp[token * 3 + 1];
    float x2 = inp[token * 3 + 2];
    float s = bvec[c];
    s = fmaf(x0, W[c], s);
    s = fmaf(x1, W[HID + c], s);
    s = fmaf(x2, W[2 * HID + c], s);
    out[(size_t)token * HID + c] = gelu_f(s);
}

// ---------------- GEMM (proven) + fp16-transpose epilogue for v-proj -------
__device__ __forceinline__ void gemm3_body(
    const float* __restrict__ A, const float* __restrict__ W,
    const float* __restrict__ bias, const float* __restrict__ res,
    float* __restrict__ out, int act, int vproj, __half* __restrict__ vhout,
    float* sm)
{
    float* Ws = sm;
    float* As = sm + 128 * 64;

    int tid = threadIdx.x, lane = tid & 31, warp = tid >> 5;
    int row0 = blockIdx.x * 32;
    int cbase = blockIdx.y * 64;

    if (vproj) {
#pragma unroll
        for (int idx = tid; idx < 128 * 16; idx += 256) {
            int k = idx >> 4, q = idx & 15;
            int c0 = cbase + q * 4;
            const float* src = W + (size_t)(c0 >> 4) * (HID * VD) + k * VD + (c0 & 15);
            *(float4*)(Ws + k * 64 + q * 4) = *(const float4*)src;
        }
    } else {
#pragma unroll
        for (int idx = tid; idx < 128 * 16; idx += 256) {
            int k = idx >> 4, q = idx & 15;
            *(float4*)(Ws + k * 64 + q * 4) = *(const float4*)(W + (size_t)k * HID + cbase + q * 4);
        }
    }
#pragma unroll
    for (int idx = tid; idx < 32 * 32; idx += 256) {
        int r = idx >> 5, q = idx & 31;
        *(float4*)(As + r * HID + q * 4) = *(const float4*)(A + (size_t)(row0 + r) * HID + q * 4);
    }
    __syncthreads();

    ull acc[4] = {0ull, 0ull, 0ull, 0ull};
    const ull* Wu = (const ull*)Ws;
    const float* a0 = As + warp * 4 * HID;

#pragma unroll 8
    for (int k = 0; k < HID; ++k) {
        ull wp = Wu[k * 32 + lane];
        float x0 = a0[0 * HID + k];
        float x1 = a0[1 * HID + k];
        float x2 = a0[2 * HID + k];
        float x3 = a0[3 * HID + k];
        acc[0] = fma2(pack2(x0, x0), wp, acc[0]);
        acc[1] = fma2(pack2(x1, x1), wp, acc[1]);
        acc[2] = fma2(pack2(x2, x2), wp, acc[2]);
        acc[3] = fma2(pack2(x3, x3), wp, acc[3]);
    }

    float b0 = 0.f, b1 = 0.f;
    if (bias) {
        float2 bv = *(const float2*)(bias + cbase + 2 * lane);
        b0 = bv.x; b1 = bv.y;
    }
#pragma unroll
    for (int i = 0; i < 4; ++i) {
        int row = row0 + warp * 4 + i;
        float o0, o1;
        unpack2(acc[i], o0, o1);
        o0 += b0; o1 += b1;
        if (res) {
            float2 rv = *(const float2*)(res + (size_t)row * HID + cbase + 2 * lane);
            o0 += rv.x; o1 += rv.y;
        }
        if (act) { o0 = gelu_f(o0); o1 = gelu_f(o1); }
        *(float2*)(out + (size_t)row * HID + cbase + 2 * lane) = make_float2(o0, o1);
        if (vhout) {
            int brow = row >> 11;         // /NN
            int n = row & (NN - 1);
            size_t basei = ((size_t)brow * HID + cbase + 2 * lane) * NN + n;
            vhout[basei]      = __float2half_rn(o0);
            vhout[basei + NN] = __float2half_rn(o1);
        }
    }
}

__global__ void __launch_bounds__(256) gemm3_kernel(
    const float* __restrict__ A, const float* __restrict__ W,
    const float* __restrict__ bias, const float* __restrict__ res,
    float* __restrict__ out, int act)
{
    extern __shared__ float sm[];
    gemm3_body(A, W, bias, res, out, act, 0, nullptr, sm);
}

// paired GEMM; z=0 v-proj also emits fp16 transposed copy for the mma kernel
__global__ void __launch_bounds__(256) gemm3p_kernel(
    const float* __restrict__ A,
    const float* __restrict__ Whead, float* __restrict__ out0, __half* __restrict__ vh,
    const float* __restrict__ W1, const float* __restrict__ b1,
    float* __restrict__ out1)
{
    extern __shared__ float sm[];
    if (blockIdx.z == 0) gemm3_body(A, Whead, nullptr, nullptr, out0, 0, 1, vh, sm);
    else                 gemm3_body(A, W1,    b1,      nullptr, out1, 0, 0, nullptr, sm);
}

// ---------------- dense attention via mma.sync (HMMA) ----------------------
// CTA = 256 thr = 8 warps = 8 heads, same 16 rows (blockIdx.x), batch z.
// m chunk [16][256] f32 staged in smem once per chunk, shared by all heads
// (8x less L2 m traffic). Per warp k-step: A frag = fp16 exp weights (16x16),
// B frag = V^T fp16 from g_vh [hd][j]; 2 HMMA accumulate 16 dims in f32.
// wsum accumulated scalar f32 per row, quad-reduced. Epilogue: /wsum + gelu.
__global__ void __launch_bounds__(256) attn_mma_kernel(
    const float* __restrict__ md, const __half* __restrict__ vh,
    const float* __restrict__ rvec, const float2* __restrict__ rs,
    float* __restrict__ out)
{
    __shared__ float m_s[16 * MS_STR];
    int b = blockIdx.y;
    int i0 = blockIdx.x * 16;
    int tid = threadIdx.x, h = tid >> 5, lane = tid & 31;
    int q = lane & 3, g = lane >> 2;

    float rr = rvec[h];
    float r2 = rr * rr;
    const float L2E = 1.4426950408889634f;
    float nr2l = -r2 * L2E;
    float msd0 = (rs[b * NN + i0 + g].x     * r2) * L2E;
    float msd1 = (rs[b * NN + i0 + g + 8].x * r2) * L2E;

    const __half* vpd0 = vh + ((size_t)b * HID + h * VD + g)     * NN;
    const __half* vpd1 = vh + ((size_t)b * HID + h * VD + g + 8) * NN;

    float d0[4] = {0.f, 0.f, 0.f, 0.f};
    float d1[4] = {0.f, 0.f, 0.f, 0.f};
    float ws0 = 0.f, ws1 = 0.f;

    const float* mrow = md + ((size_t)(b * NN + i0)) * NN;

    int sr = tid >> 4, sc = (tid & 15) * 4;   // staging: row, col4

    for (int ch = 0; ch < NN / MCH; ++ch) {
        __syncthreads();
        {
            const float* src = mrow + (size_t)sr * NN + ch * MCH + sc;
            float* dst = m_s + sr * MS_STR + sc;
#pragma unroll
            for (int i = 0; i < 4; ++i)
                *(float4*)(dst + 64 * i) = *(const float4*)(src + 64 * i);
        }
        __syncthreads();

#pragma unroll 4
        for (int t = 0; t < MCH / 16; ++t) {
            int jl = t * 16 + q * 2;
            const float* mp0 = m_s + g * MS_STR + jl;
            const float* mp1 = m_s + (g + 8) * MS_STR + jl;
            float2 ma0 = *(const float2*)(mp0);
            float2 ma1 = *(const float2*)(mp1);
            float2 ma2 = *(const float2*)(mp0 + 8);
            float2 ma3 = *(const float2*)(mp1 + 8);

            float w00 = ex2f(fmaf(ma0.x, nr2l, msd0));
            float w01 = ex2f(fmaf(ma0.y, nr2l, msd0));
            float w10 = ex2f(fmaf(ma1.x, nr2l, msd1));
            float w11 = ex2f(fmaf(ma1.y, nr2l, msd1));
            float w20 = ex2f(fmaf(ma2.x, nr2l, msd0));
            float w21 = ex2f(fmaf(ma2.y, nr2l, msd0));
            float w30 = ex2f(fmaf(ma3.x, nr2l, msd1));
            float w31 = ex2f(fmaf(ma3.y, nr2l, msd1));
            ws0 += (w00 + w01) + (w20 + w21);
            ws1 += (w10 + w11) + (w30 + w31);

            unsigned a0 = h2u(__floats2half2_rn(w00, w01));
            unsigned a1 = h2u(__floats2half2_rn(w10, w11));
            unsigned a2 = h2u(__floats2half2_rn(w20, w21));
            unsigned a3 = h2u(__floats2half2_rn(w30, w31));

            int j = ch * MCH + t * 16 + q * 2;
            unsigned b00 = *(const unsigned*)(vpd0 + j);
            unsigned b01 = *(const unsigned*)(vpd0 + j + 8);
            unsigned b10 = *(const unsigned*)(vpd1 + j);
            unsigned b11 = *(const unsigned*)(vpd1 + j + 8);

            mma16816(d0, a0, a1, a2, a3, b00, b01);
            mma16816(d1, a0, a1, a2, a3, b10, b11);
        }
    }

    // reduce wsum within each quad (lanes sharing g)
    ws0 += __shfl_xor_sync(FULLMASK, ws0, 1);
    ws0 += __shfl_xor_sync(FULLMASK, ws0, 2);
    ws1 += __shfl_xor_sync(FULLMASK, ws1, 1);
    ws1 += __shfl_xor_sync(FULLMASK, ws1, 2);
    float inv0 = 1.0f / ws0;
    float inv1 = 1.0f / ws1;

    float* o0 = out + (size_t)(b * NN + i0 + g) * HID + h * VD;
    float* o1 = out + (size_t)(b * NN + i0 + g + 8) * HID + h * VD;
    *(float2*)(o0 + 2 * q)     = make_float2(gelu_f(d0[0] * inv0), gelu_f(d0[1] * inv0));
    *(float2*)(o0 + 8 + 2 * q) = make_float2(gelu_f(d1[0] * inv0), gelu_f(d1[1] * inv0));
    *(float2*)(o1 + 2 * q)     = make_float2(gelu_f(d0[2] * inv1), gelu_f(d0[3] * inv1));
    *(float2*)(o1 + 8 + 2 * q) = make_float2(gelu_f(d1[2] * inv1), gelu_f(d1[3] * inv1));
}

// ---------------- sparse (masked) attention ----------------
__global__ void __launch_bounds__(256) attn_sparse_kernel(
    const float* __restrict__ v, const float* __restrict__ rvec,
    const float2* __restrict__ rs,
    const int* __restrict__ sidx, const float* __restrict__ smv,
    float* __restrict__ out)
{
    int b = blockIdx.z, h = blockIdx.y;
    float rr = rvec[h];
    float r2 = rr * rr;
    const float L2E = 1.4426950408889634f;
    float nr2l = -r2 * L2E;

    int lane = threadIdx.x & 31, warp = threadIdx.x >> 5;
    int i = blockIdx.x * 8 + warp;
    int grow = b * NN + i;

    float msdl = (rs[grow].x * r2) * L2E;
    const int*   ip = sidx + (size_t)grow * 128;
    const float* mp = smv  + (size_t)grow * 128;
    const float* vbase = v + (size_t)b * NN * HID + h * VD;

    ull acc[8];
#pragma unroll
    for (int d = 0; d < 8; ++d) acc[d] = 0ull;
    float wsum = 0.f;

#pragma unroll
    for (int t = 0; t < 4; ++t) {
        int k = t * 32 + lane;
        int idx = ip[k];
        float m = mp[k];
        float w = ex2f(fmaf(m, nr2l, msdl));
        wsum += w;
        const ulonglong2* vp = (const ulonglong2*)(vbase + (size_t)idx * HID);
        ulonglong2 p0 = vp[0], p1 = vp[1], p2 = vp[2], p3 = vp[3];
        ull wp = pack2(w, w);
        acc[0] = fma2(wp, p0.x, acc[0]);
        acc[1] = fma2(wp, p0.y, acc[1]);
        acc[2] = fma2(wp, p1.x, acc[2]);
        acc[3] = fma2(wp, p1.y, acc[3]);
        acc[4] = fma2(wp, p2.x, acc[4]);
        acc[5] = fma2(wp, p2.y, acc[5]);
        acc[6] = fma2(wp, p3.x, acc[6]);
        acc[7] = fma2(wp, p3.y, acc[7]);
    }

#pragma unroll
    for (int off = 16; off; off >>= 1) {
        wsum += __shfl_xor_sync(FULLMASK, wsum, off);
#pragma unroll
        for (int d = 0; d < 8; ++d) {
            ull o = __shfl_xor_sync(FULLMASK, acc[d], off);
            acc[d] = add2(acc[d], o);
        }
    }

    if (lane == 0) {
        float inv = 1.0f / wsum;
        float o[16];
#pragma unroll
        for (int d = 0; d < 8; ++d) unpack2(acc[d], o[2 * d], o[2 * d + 1]);
#pragma unroll
        for (int e = 0; e < 16; ++e) o[e] = gelu_f(o[e] * inv);
        float* dst = out + (size_t)grow * HID + h * VD;
        *(float4*)(dst + 0)  = make_float4(o[0],  o[1],  o[2],  o[3]);
        *(float4*)(dst + 4)  = make_float4(o[4],  o[5],  o[6],  o[7]);
        *(float4*)(dst + 8)  = make_float4(o[8],  o[9],  o[10], o[11]);
        *(float4*)(dst + 12) = make_float4(o[12], o[13], o[14], o[15]);
    }
}

// ---------------- final 128 -> 1 projection ----------------
__global__ void final_kernel(const float* __restrict__ t, const float* __restrict__ W,
                             const float* __restrict__ bvec, float* __restrict__ out) {
    int warp = threadIdx.x >> 5, lane = threadIdx.x & 31;
    int token = blockIdx.x * 8 + warp;
    const float* p = t + (size_t)token * HID;
    float s = 0.f;
#pragma unroll
    for (int i = 0; i < 4; ++i) s = fmaf(p[lane + 32 * i], W[lane + 32 * i], s);
#pragma unroll
    for (int off = 16; off; off >>= 1) s += __shfl_xor_sync(FULLMASK, s, off);
    if (lane == 0) out[token] = s + bvec[0];
}

// ---------------- orchestration ----------------
static float* symf(const void* sym) {
    void* p = nullptr;
    cudaGetSymbolAddress(&p, sym);
    return (float*)p;
}

extern "C" void kernel_launch(void* const* d_in, const int* in_sizes, int n_in,
                              void* d_out, int out_size) {
    const float* md      = (const float*)d_in[0];
    const float* inputs  = (const float*)d_in[1];
    const float* en_W    = (const float*)d_in[2];
    const float* en_b    = (const float*)d_in[3];
    const float* down_r  = (const float*)d_in[4];
    const float* down_w  = (const float*)d_in[5];
    const float* mlp1_W1 = (const float*)d_in[6];
    const float* mlp1_b1 = (const float*)d_in[7];
    const float* mlp1_W2 = (const float*)d_in[8];
    const float* mlp1_b2 = (const float*)d_in[9];
    const float* w1_W    = (const float*)d_in[10];
    const float* w1_b    = (const float*)d_in[11];
    const float* pa_r    = (const float*)d_in[12];
    const float* pa_w    = (const float*)d_in[13];
    const float* blk_W1  = (const float*)d_in[14];
    const float* blk_b1  = (const float*)d_in[15];
    const float* blk_W2  = (const float*)d_in[16];
    const float* blk_b2  = (const float*)d_in[17];
    const float* wi_W    = (const float*)d_in[18];
    const float* wi_b    = (const float*)d_in[19];
    const float* up_r    = (const float*)d_in[20];
    const float* up_w    = (const float*)d_in[21];
    const float* mlp2_W1 = (const float*)d_in[22];
    const float* mlp2_b1 = (const float*)d_in[23];
    const float* mlp2_W2 = (const float*)d_in[24];
    const float* mlp2_b2 = (const float*)d_in[25];
    const float* w2_W    = (const float*)d_in[26];
    const float* w2_b    = (const float*)d_in[27];
    const float* de_W1   = (const float*)d_in[28];
    const float* de_b1   = (const float*)d_in[29];
    const float* de_W2   = (const float*)d_in[30];
    const float* de_b2   = (const float*)d_in[31];
    float* outp = (float*)d_out;

    float*  en = symf(g_en);
    float*  x  = symf(g_x);
    float*  hb = symf(g_h);
    float*  tb = symf(g_t);
    float*  rb = symf(g_r);
    float*  vb = symf(g_v);
    __half* vh;
    { void* p = nullptr; cudaGetSymbolAddress(&p, g_vh); vh = (__half*)p; }
    float2* rsp;
    { void* p = nullptr; cudaGetSymbolAddress(&p, g_rowstats); rsp = (float2*)p; }
    int* sidx;
    { void* p = nullptr; cudaGetSymbolAddress(&p, g_sidx); sidx = (int*)p; }
    float* smv = symf(g_sm);

    cudaFuncSetAttribute(gemm3_kernel,  cudaFuncAttributeMaxDynamicSharedMemorySize, GEMM_SMEM);
    cudaFuncSetAttribute(gemm3p_kernel, cudaFuncAttributeMaxDynamicSharedMemorySize, GEMM_SMEM);

    dim3 ggrid(BN / 32, 2);
    dim3 pgrid(BN / 32, 2, 2);
    dim3 mgrid(NN / 16, BB);
    dim3 sgrid(NN / 8, HH, BB);

    rowstats_kernel<<<BN / 8, 256>>>(md, rsp);
    sparse_idx_kernel<<<BN / 8, 256>>>(md, rsp, sidx, smv);
    enc_kernel<<<BN, HID>>>(inputs, en_W, en_b, en);

    // ---- stage 1 (masked -> sparse) ----
    gemm3p_kernel<<<pgrid, 256, GEMM_SMEM>>>(en, down_w, vb, vh, w1_W, w1_b, rb);
    attn_sparse_kernel<<<sgrid, 256>>>(vb, down_r, rsp, sidx, smv, hb);
    gemm3_kernel<<<ggrid, 256, GEMM_SMEM>>>(hb, mlp1_W1, mlp1_b1, nullptr, tb, 1);
    gemm3_kernel<<<ggrid, 256, GEMM_SMEM>>>(tb, mlp1_W2, mlp1_b2, rb, x, 1);

    // ---- 4 unmasked blocks (HMMA dense attention) ----
    for (int i = 0; i < 4; ++i) {
        gemm3p_kernel<<<pgrid, 256, GEMM_SMEM>>>(x, pa_w + (size_t)i * HH * HID * VD, vb, vh,
            wi_W + (size_t)i * HID * HID, wi_b + (size_t)i * HID, rb);
        attn_mma_kernel<<<mgrid, 256>>>(md, vh, pa_r + (size_t)i * HH, rsp, hb);
        gemm3_kernel<<<ggrid, 256, GEMM_SMEM>>>(hb, blk_W1 + (size_t)i * HID * HID, blk_b1 + (size_t)i * HID, nullptr, tb, 1);
        gemm3_kernel<<<ggrid, 256, GEMM_SMEM>>>(tb, blk_W2 + (size_t)i * HID * HID, blk_b2 + (size_t)i * HID, rb, x, 1);
    }

    // ---- stage 2 (masked -> sparse) ----
    gemm3p_kernel<<<pgrid, 256, GEMM_SMEM>>>(x, up_w, vb, vh, w2_W, w2_b, rb);
    attn_sparse_kernel<<<sgrid, 256>>>(vb, up_r, rsp, sidx, smv, hb);
    gemm3_kernel<<<ggrid, 256, GEMM_SMEM>>>(hb, mlp2_W1, mlp2_b1, nullptr, tb, 1);
    gemm3_kernel<<<ggrid, 256, GEMM_SMEM>>>(tb, mlp2_W2, mlp2_b2, rb, x, 1);

    // ---- decoder ----
    gemm3_kernel<<<ggrid, 256, GEMM_SMEM>>>(x, de_W1, de_b1, nullptr, tb, 1);
    final_kernel<<<BN / 8, 256>>>(tb, de_W2, de_b2, outp);
}

// round 17
// speedup vs baseline: 1.7111x; 1.0651x over previous
#include <cuda_runtime.h>
#include <cuda_fp16.h>
#include <math.h>

#define FULLMASK 0xffffffffu

#define BB   2
#define NN   2048
#define HH   8
#define HID  128
#define VD   16
#define BN   (BB * NN)
#define KTH  103

#define GEMM_SMEM (32768 + 16384)
#define MCH    256
#define MS_STR 264

typedef unsigned long long ull;

__device__ float  g_en[BN * HID];
__device__ float  g_x [BN * HID];
__device__ float  g_h [BN * HID];
__device__ float  g_t [BN * HID];
__device__ float  g_r [BN * HID];
__device__ float  g_v [BN * HID];
__device__ __half g_vh[BN * HID];   // v transposed per head: [b][hd][j] fp16
__device__ float2 g_rowstats[BN];
__device__ int    g_sidx[BN * 128];
__device__ float  g_sm  [BN * 128];

// ---------------- helpers ----------------
__device__ __forceinline__ ull pack2(float x, float y) {
    ull r;
    asm("mov.b64 %0, {%1, %2};" : "=l"(r) : "r"(__float_as_uint(x)), "r"(__float_as_uint(y)));
    return r;
}
__device__ __forceinline__ void unpack2(ull u, float& x, float& y) {
    unsigned a, b;
    asm("mov.b64 {%0, %1}, %2;" : "=r"(a), "=r"(b) : "l"(u));
    x = __uint_as_float(a); y = __uint_as_float(b);
}
__device__ __forceinline__ ull fma2(ull a, ull b, ull c) {
    ull d;
    asm("fma.rn.f32x2 %0, %1, %2, %3;" : "=l"(d) : "l"(a), "l"(b), "l"(c));
    return d;
}
__device__ __forceinline__ ull add2(ull a, ull b) {
    ull d;
    asm("add.rn.f32x2 %0, %1, %2;" : "=l"(d) : "l"(a), "l"(b));
    return d;
}
__device__ __forceinline__ float ex2f(float x) {
    float r;
    asm("ex2.approx.f32 %0, %1;" : "=f"(r) : "f"(x));
    return r;
}
__device__ __forceinline__ float gelu_f(float x) {
    return 0.5f * x * (1.0f + erff(x * 0.70710678118654752f));
}
__device__ __forceinline__ unsigned h2u(__half2 h) {
    unsigned u;
    asm("mov.b32 %0, %1;" : "=r"(u) : "r"(*(unsigned*)&h));
    return u;
}
// mma.sync m16n8k16 row.col f32 += f16*f16 (HMMA on sm_103)
__device__ __forceinline__ void mma16816(float d[4],
    unsigned a0, unsigned a1, unsigned a2, unsigned a3,
    unsigned b0, unsigned b1)
{
    asm volatile(
        "mma.sync.aligned.m16n8k16.row.col.f32.f16.f16.f32 "
        "{%0,%1,%2,%3}, {%4,%5,%6,%7}, {%8,%9}, {%0,%1,%2,%3};"
        : "+f"(d[0]), "+f"(d[1]), "+f"(d[2]), "+f"(d[3])
        : "r"(a0), "r"(a1), "r"(a2), "r"(a3), "r"(b0), "r"(b1));
}

// ---------------- per-row order statistics of m_dist ----------------
__global__ void rowstats_kernel(const float* __restrict__ md, float2* __restrict__ rs) {
    int warp = threadIdx.x >> 5, lane = threadIdx.x & 31;
    int row = blockIdx.x * 8 + warp;
    const float* p = md + (size_t)row * NN + lane;
    unsigned mu[64];
    float mn = 1e30f;
#pragma unroll
    for (int i = 0; i < 64; ++i) {
        float x = p[i * 32];
        mn = fminf(mn, x);
        mu[i] = __float_as_uint(x);
    }
#pragma unroll
    for (int off = 16; off; off >>= 1)
        mn = fminf(mn, __shfl_xor_sync(FULLMASK, mn, off));

    unsigned lo = 0u, hi = 0x3F800000u;
    while (hi - lo > 1u) {
        unsigned mid = (lo + hi) >> 1;
        int c = 0;
#pragma unroll
        for (int i = 0; i < 64; ++i) c += (mu[i] <= mid) ? 1 : 0;
        c = __reduce_add_sync(FULLMASK, c);
        if (c >= KTH) hi = mid; else lo = mid;
    }
    if (lane == 0) rs[row] = make_float2(mn, __uint_as_float(hi));
}

// ---------------- masked-set compaction ----------------
__global__ void sparse_idx_kernel(const float* __restrict__ md,
                                  const float2* __restrict__ rs,
                                  int* __restrict__ sidx, float* __restrict__ smv) {
    int warp = threadIdx.x >> 5, lane = threadIdx.x & 31;
    int row = blockIdx.x * 8 + warp;
    float thr = rs[row].y;
    const float* p = md + (size_t)row * NN;
    int base = 0;
#pragma unroll 4
    for (int t = 0; t < 64; ++t) {
        int j = t * 32 + lane;
        float m = p[j];
        bool sel = (m <= thr);
        unsigned mask = __ballot_sync(FULLMASK, sel);
        if (sel) {
            int pos = base + __popc(mask & ((1u << lane) - 1u));
            sidx[(size_t)row * 128 + pos] = j;
            smv [(size_t)row * 128 + pos] = m;
        }
        base += __popc(mask);
    }
    for (int k = base + lane; k < 128; k += 32) {
        sidx[(size_t)row * 128 + k] = 0;
        smv [(size_t)row * 128 + k] = 1e30f;
    }
}

// ---------------- encoder ----------------
__global__ void enc_kernel(const float* __restrict__ inp, const float* __restrict__ W,
                           const float* __restrict__ bvec, float* __restrict__ out) {
    int token = blockIdx.x, c = threadIdx.x;
    float x0 = inp[token * 3 + 0];
    float x1 = inp[token * 3 + 1];
    float x2 = inp[token * 3 + 2];
    float s = bvec[c];
    s = fmaf(x0, W[c], s);
    s = fmaf(x1, W[HID + c], s);
    s = fmaf(x2, W[2 * HID + c], s);
    out[(size_t)token * HID + c] = gelu_f(s);
}

// ---------------- GEMM (proven) + fp16-transpose epilogue for v-proj -------
__device__ __forceinline__ void gemm3_body(
    const float* __restrict__ A, const float* __restrict__ W,
    const float* __restrict__ bias, const float* __restrict__ res,
    float* __restrict__ out, int act, int vproj, __half* __restrict__ vhout,
    float* sm)
{
    float* Ws = sm;
    float* As = sm + 128 * 64;

    int tid = threadIdx.x, lane = tid & 31, warp = tid >> 5;
    int row0 = blockIdx.x * 32;
    int cbase = blockIdx.y * 64;

    if (vproj) {
#pragma unroll
        for (int idx = tid; idx < 128 * 16; idx += 256) {
            int k = idx >> 4, q = idx & 15;
            int c0 = cbase + q * 4;
            const float* src = W + (size_t)(c0 >> 4) * (HID * VD) + k * VD + (c0 & 15);
            *(float4*)(Ws + k * 64 + q * 4) = *(const float4*)src;
        }
    } else {
#pragma unroll
        for (int idx = tid; idx < 128 * 16; idx += 256) {
            int k = idx >> 4, q = idx & 15;
            *(float4*)(Ws + k * 64 + q * 4) = *(const float4*)(W + (size_t)k * HID + cbase + q * 4);
        }
    }
#pragma unroll
    for (int idx = tid; idx < 32 * 32; idx += 256) {
        int r = idx >> 5, q = idx & 31;
        *(float4*)(As + r * HID + q * 4) = *(const float4*)(A + (size_t)(row0 + r) * HID + q * 4);
    }
    __syncthreads();

    ull acc[4] = {0ull, 0ull, 0ull, 0ull};
    const ull* Wu = (const ull*)Ws;
    const float* a0 = As + warp * 4 * HID;

#pragma unroll 8
    for (int k = 0; k < HID; ++k) {
        ull wp = Wu[k * 32 + lane];
        float x0 = a0[0 * HID + k];
        float x1 = a0[1 * HID + k];
        float x2 = a0[2 * HID + k];
        float x3 = a0[3 * HID + k];
        acc[0] = fma2(pack2(x0, x0), wp, acc[0]);
        acc[1] = fma2(pack2(x1, x1), wp, acc[1]);
        acc[2] = fma2(pack2(x2, x2), wp, acc[2]);
        acc[3] = fma2(pack2(x3, x3), wp, acc[3]);
    }

    float b0 = 0.f, b1 = 0.f;
    if (bias) {
        float2 bv = *(const float2*)(bias + cbase + 2 * lane);
        b0 = bv.x; b1 = bv.y;
    }
#pragma unroll
    for (int p = 0; p < 2; ++p) {
        int rowA = row0 + warp * 4 + 2 * p;
        float oA0, oA1, oB0, oB1;
        unpack2(acc[2 * p],     oA0, oA1);
        unpack2(acc[2 * p + 1], oB0, oB1);
        oA0 += b0; oA1 += b1; oB0 += b0; oB1 += b1;
        if (res) {
            float2 rA = *(const float2*)(res + (size_t)rowA * HID + cbase + 2 * lane);
            float2 rB = *(const float2*)(res + (size_t)(rowA + 1) * HID + cbase + 2 * lane);
            oA0 += rA.x; oA1 += rA.y; oB0 += rB.x; oB1 += rB.y;
        }
        if (act) { oA0 = gelu_f(oA0); oA1 = gelu_f(oA1); oB0 = gelu_f(oB0); oB1 = gelu_f(oB1); }
        *(float2*)(out + (size_t)rowA * HID + cbase + 2 * lane)       = make_float2(oA0, oA1);
        *(float2*)(out + (size_t)(rowA + 1) * HID + cbase + 2 * lane) = make_float2(oB0, oB1);
        if (vhout) {
            int brow = rowA >> 11;        // /NN
            int n = rowA & (NN - 1);      // even; n+1 same batch
            size_t basei = ((size_t)brow * HID + cbase + 2 * lane) * NN + n;
            *(__half2*)(vhout + basei)      = __floats2half2_rn(oA0, oB0);
            *(__half2*)(vhout + basei + NN) = __floats2half2_rn(oA1, oB1);
        }
    }
}

__global__ void __launch_bounds__(256) gemm3_kernel(
    const float* __restrict__ A, const float* __restrict__ W,
    const float* __restrict__ bias, const float* __restrict__ res,
    float* __restrict__ out, int act)
{
    extern __shared__ float sm[];
    gemm3_body(A, W, bias, res, out, act, 0, nullptr, sm);
}

// paired GEMM; z=0 v-proj optionally emits fp16 transposed copy (vh) for mma
__global__ void __launch_bounds__(256) gemm3p_kernel(
    const float* __restrict__ A,
    const float* __restrict__ Whead, float* __restrict__ out0, __half* __restrict__ vh,
    const float* __restrict__ W1, const float* __restrict__ b1,
    float* __restrict__ out1)
{
    extern __shared__ float sm[];
    if (blockIdx.z == 0) gemm3_body(A, Whead, nullptr, nullptr, out0, 0, 1, vh, sm);
    else                 gemm3_body(A, W1,    b1,      nullptr, out1, 0, 0, nullptr, sm);
}

// ---------------- dense attention via mma.sync (HMMA), v2 ------------------
// CTA = 128 thr = 4 warps = 4 heads (head group blockIdx.y), same 16 rows.
// m chunk [16][256] double-buffered in smem (LDG of chunk c+1 into regs
// before compute of chunk c); B fragments prefetched one step ahead.
// Grid 512 CTAs -> 3.46 CTAs/SM wave balance.
__global__ void __launch_bounds__(128) attn_mma_kernel(
    const float* __restrict__ md, const __half* __restrict__ vh,
    const float* __restrict__ rvec, const float2* __restrict__ rs,
    float* __restrict__ out)
{
    __shared__ float m_s[2][16 * MS_STR];
    int b = blockIdx.z, hg = blockIdx.y;
    int i0 = blockIdx.x * 16;
    int tid = threadIdx.x, warp = tid >> 5, lane = tid & 31;
    int h = hg * 4 + warp;
    int q = lane & 3, g = lane >> 2;

    float rr = rvec[h];
    float r2 = rr * rr;
    const float L2E = 1.4426950408889634f;
    float nr2l = -r2 * L2E;
    float msd0 = (rs[b * NN + i0 + g].x     * r2) * L2E;
    float msd1 = (rs[b * NN + i0 + g + 8].x * r2) * L2E;

    const __half* vpd0 = vh + ((size_t)b * HID + h * VD + g)     * NN;
    const __half* vpd1 = vh + ((size_t)b * HID + h * VD + g + 8) * NN;

    float d0[4] = {0.f, 0.f, 0.f, 0.f};
    float d1[4] = {0.f, 0.f, 0.f, 0.f};
    float ws0 = 0.f, ws1 = 0.f;

    const float* mrow = md + ((size_t)(b * NN + i0)) * NN;

    int sr = tid >> 3, sc = (tid & 7) * 4;   // staging: 16 rows, 8 col4-slots

    // stage chunk 0
    {
        const float* src = mrow + (size_t)sr * NN + sc;
        float* dst = m_s[0] + sr * MS_STR + sc;
#pragma unroll
        for (int i = 0; i < 8; ++i)
            *(float4*)(dst + 32 * i) = *(const float4*)(src + 32 * i);
    }
    __syncthreads();

    // preload B frags for step 0
    unsigned b00 = *(const unsigned*)(vpd0 + q * 2);
    unsigned b01 = *(const unsigned*)(vpd0 + q * 2 + 8);
    unsigned b10 = *(const unsigned*)(vpd1 + q * 2);
    unsigned b11 = *(const unsigned*)(vpd1 + q * 2 + 8);

    for (int ch = 0; ch < NN / MCH; ++ch) {
        int cur = ch & 1;
        float4 pre[8];
        if (ch < NN / MCH - 1) {
            const float* src = mrow + (size_t)sr * NN + (ch + 1) * MCH + sc;
#pragma unroll
            for (int i = 0; i < 8; ++i) pre[i] = *(const float4*)(src + 32 * i);
        }

#pragma unroll 4
        for (int t = 0; t < MCH / 16; ++t) {
            int gt = ch * (MCH / 16) + t;
            // prefetch B frags for step gt+1 (clamped)
            int jn = (gt + 1 < NN / 16) ? (gt + 1) * 16 + q * 2 : q * 2;
            unsigned n00 = *(const unsigned*)(vpd0 + jn);
            unsigned n01 = *(const unsigned*)(vpd0 + jn + 8);
            unsigned n10 = *(const unsigned*)(vpd1 + jn);
            unsigned n11 = *(const unsigned*)(vpd1 + jn + 8);

            int jl = t * 16 + q * 2;
            const float* mp0 = m_s[cur] + g * MS_STR + jl;
            const float* mp1 = m_s[cur] + (g + 8) * MS_STR + jl;
            float2 ma0 = *(const float2*)(mp0);
            float2 ma1 = *(const float2*)(mp1);
            float2 ma2 = *(const float2*)(mp0 + 8);
            float2 ma3 = *(const float2*)(mp1 + 8);

            float w00 = ex2f(fmaf(ma0.x, nr2l, msd0));
            float w01 = ex2f(fmaf(ma0.y, nr2l, msd0));
            float w10 = ex2f(fmaf(ma1.x, nr2l, msd1));
            float w11 = ex2f(fmaf(ma1.y, nr2l, msd1));
            float w20 = ex2f(fmaf(ma2.x, nr2l, msd0));
            float w21 = ex2f(fmaf(ma2.y, nr2l, msd0));
            float w30 = ex2f(fmaf(ma3.x, nr2l, msd1));
            float w31 = ex2f(fmaf(ma3.y, nr2l, msd1));
            ws0 += (w00 + w01) + (w20 + w21);
            ws1 += (w10 + w11) + (w30 + w31);

            unsigned a0 = h2u(__floats2half2_rn(w00, w01));
            unsigned a1 = h2u(__floats2half2_rn(w10, w11));
            unsigned a2 = h2u(__floats2half2_rn(w20, w21));
            unsigned a3 = h2u(__floats2half2_rn(w30, w31));

            mma16816(d0, a0, a1, a2, a3, b00, b01);
            mma16816(d1, a0, a1, a2, a3, b10, b11);

            b00 = n00; b01 = n01; b10 = n10; b11 = n11;
        }

        if (ch < NN / MCH - 1) {
            float* dst = m_s[cur ^ 1] + sr * MS_STR + sc;
#pragma unroll
            for (int i = 0; i < 8; ++i) *(float4*)(dst + 32 * i) = pre[i];
        }
        __syncthreads();
    }

    // reduce wsum within each quad (lanes sharing g)
    ws0 += __shfl_xor_sync(FULLMASK, ws0, 1);
    ws0 += __shfl_xor_sync(FULLMASK, ws0, 2);
    ws1 += __shfl_xor_sync(FULLMASK, ws1, 1);
    ws1 += __shfl_xor_sync(FULLMASK, ws1, 2);
    float inv0 = 1.0f / ws0;
    float inv1 = 1.0f / ws1;

    float* o0 = out + (size_t)(b * NN + i0 + g) * HID + h * VD;
    float* o1 = out + (size_t)(b * NN + i0 + g + 8) * HID + h * VD;
    *(float2*)(o0 + 2 * q)     = make_float2(gelu_f(d0[0] * inv0), gelu_f(d0[1] * inv0));
    *(float2*)(o0 + 8 + 2 * q) = make_float2(gelu_f(d1[0] * inv0), gelu_f(d1[1] * inv0));
    *(float2*)(o1 + 2 * q)     = make_float2(gelu_f(d0[2] * inv1), gelu_f(d0[3] * inv1));
    *(float2*)(o1 + 8 + 2 * q) = make_float2(gelu_f(d1[2] * inv1), gelu_f(d1[3] * inv1));
}

// ---------------- sparse (masked) attention ----------------
__global__ void __launch_bounds__(256) attn_sparse_kernel(
    const float* __restrict__ v, const float* __restrict__ rvec,
    const float2* __restrict__ rs,
    const int* __restrict__ sidx, const float* __restrict__ smv,
    float* __restrict__ out)
{
    int b = blockIdx.z, h = blockIdx.y;
    float rr = rvec[h];
    float r2 = rr * rr;
    const float L2E = 1.4426950408889634f;
    float nr2l = -r2 * L2E;

    int lane = threadIdx.x & 31, warp = threadIdx.x >> 5;
    int i = blockIdx.x * 8 + warp;
    int grow = b * NN + i;

    float msdl = (rs[grow].x * r2) * L2E;
    const int*   ip = sidx + (size_t)grow * 128;
    const float* mp = smv  + (size_t)grow * 128;
    const float* vbase = v + (size_t)b * NN * HID + h * VD;

    ull acc[8];
#pragma unroll
    for (int d = 0; d < 8; ++d) acc[d] = 0ull;
    float wsum = 0.f;

#pragma unroll
    for (int t = 0; t < 4; ++t) {
        int k = t * 32 + lane;
        int idx = ip[k];
        float m = mp[k];
        float w = ex2f(fmaf(m, nr2l, msdl));
        wsum += w;
        const ulonglong2* vp = (const ulonglong2*)(vbase + (size_t)idx * HID);
        ulonglong2 p0 = vp[0], p1 = vp[1], p2 = vp[2], p3 = vp[3];
        ull wp = pack2(w, w);
        acc[0] = fma2(wp, p0.x, acc[0]);
        acc[1] = fma2(wp, p0.y, acc[1]);
        acc[2] = fma2(wp, p1.x, acc[2]);
        acc[3] = fma2(wp, p1.y, acc[3]);
        acc[4] = fma2(wp, p2.x, acc[4]);
        acc[5] = fma2(wp, p2.y, acc[5]);
        acc[6] = fma2(wp, p3.x, acc[6]);
        acc[7] = fma2(wp, p3.y, acc[7]);
    }

#pragma unroll
    for (int off = 16; off; off >>= 1) {
        wsum += __shfl_xor_sync(FULLMASK, wsum, off);
#pragma unroll
        for (int d = 0; d < 8; ++d) {
            ull o = __shfl_xor_sync(FULLMASK, acc[d], off);
            acc[d] = add2(acc[d], o);
        }
    }

    if (lane == 0) {
        float inv = 1.0f / wsum;
        float o[16];
#pragma unroll
        for (int d = 0; d < 8; ++d) unpack2(acc[d], o[2 * d], o[2 * d + 1]);
#pragma unroll
        for (int e = 0; e < 16; ++e) o[e] = gelu_f(o[e] * inv);
        float* dst = out + (size_t)grow * HID + h * VD;
        *(float4*)(dst + 0)  = make_float4(o[0],  o[1],  o[2],  o[3]);
        *(float4*)(dst + 4)  = make_float4(o[4],  o[5],  o[6],  o[7]);
        *(float4*)(dst + 8)  = make_float4(o[8],  o[9],  o[10], o[11]);
        *(float4*)(dst + 12) = make_float4(o[12], o[13], o[14], o[15]);
    }
}

// ---------------- final 128 -> 1 projection ----------------
__global__ void final_kernel(const float* __restrict__ t, const float* __restrict__ W,
                             const float* __restrict__ bvec, float* __restrict__ out) {
    int warp = threadIdx.x >> 5, lane = threadIdx.x & 31;
    int token = blockIdx.x * 8 + warp;
    const float* p = t + (size_t)token * HID;
    float s = 0.f;
#pragma unroll
    for (int i = 0; i < 4; ++i) s = fmaf(p[lane + 32 * i], W[lane + 32 * i], s);
#pragma unroll
    for (int off = 16; off; off >>= 1) s += __shfl_xor_sync(FULLMASK, s, off);
    if (lane == 0) out[token] = s + bvec[0];
}

// ---------------- orchestration ----------------
static float* symf(const void* sym) {
    void* p = nullptr;
    cudaGetSymbolAddress(&p, sym);
    return (float*)p;
}

extern "C" void kernel_launch(void* const* d_in, const int* in_sizes, int n_in,
                              void* d_out, int out_size) {
    const float* md      = (const float*)d_in[0];
    const float* inputs  = (const float*)d_in[1];
    const float* en_W    = (const float*)d_in[2];
    const float* en_b    = (const float*)d_in[3];
    const float* down_r  = (const float*)d_in[4];
    const float* down_w  = (const float*)d_in[5];
    const float* mlp1_W1 = (const float*)d_in[6];
    const float* mlp1_b1 = (const float*)d_in[7];
    const float* mlp1_W2 = (const float*)d_in[8];
    const float* mlp1_b2 = (const float*)d_in[9];
    const float* w1_W    = (const float*)d_in[10];
    const float* w1_b    = (const float*)d_in[11];
    const float* pa_r    = (const float*)d_in[12];
    const float* pa_w    = (const float*)d_in[13];
    const float* blk_W1  = (const float*)d_in[14];
    const float* blk_b1  = (const float*)d_in[15];
    const float* blk_W2  = (const float*)d_in[16];
    const float* blk_b2  = (const float*)d_in[17];
    const float* wi_W    = (const float*)d_in[18];
    const float* wi_b    = (const float*)d_in[19];
    const float* up_r    = (const float*)d_in[20];
    const float* up_w    = (const float*)d_in[21];
    const float* mlp2_W1 = (const float*)d_in[22];
    const float* mlp2_b1 = (const float*)d_in[23];
    const float* mlp2_W2 = (const float*)d_in[24];
    const float* mlp2_b2 = (const float*)d_in[25];
    const float* w2_W    = (const float*)d_in[26];
    const float* w2_b    = (const float*)d_in[27];
    const float* de_W1   = (const float*)d_in[28];
    const float* de_b1   = (const float*)d_in[29];
    const float* de_W2   = (const float*)d_in[30];
    const float* de_b2   = (const float*)d_in[31];
    float* outp = (float*)d_out;

    float*  en = symf(g_en);
    float*  x  = symf(g_x);
    float*  hb = symf(g_h);
    float*  tb = symf(g_t);
    float*  rb = symf(g_r);
    float*  vb = symf(g_v);
    __half* vh;
    { void* p = nullptr; cudaGetSymbolAddress(&p, g_vh); vh = (__half*)p; }
    float2* rsp;
    { void* p = nullptr; cudaGetSymbolAddress(&p, g_rowstats); rsp = (float2*)p; }
    int* sidx;
    { void* p = nullptr; cudaGetSymbolAddress(&p, g_sidx); sidx = (int*)p; }
    float* smv = symf(g_sm);

    cudaFuncSetAttribute(gemm3_kernel,  cudaFuncAttributeMaxDynamicSharedMemorySize, GEMM_SMEM);
    cudaFuncSetAttribute(gemm3p_kernel, cudaFuncAttributeMaxDynamicSharedMemorySize, GEMM_SMEM);

    dim3 ggrid(BN / 32, 2);
    dim3 pgrid(BN / 32, 2, 2);
    dim3 mgrid(NN / 16, HH / 4, BB);
    dim3 sgrid(NN / 8, HH, BB);

    rowstats_kernel<<<BN / 8, 256>>>(md, rsp);
    sparse_idx_kernel<<<BN / 8, 256>>>(md, rsp, sidx, smv);
    enc_kernel<<<BN, HID>>>(inputs, en_W, en_b, en);

    // ---- stage 1 (masked -> sparse; no vh needed) ----
    gemm3p_kernel<<<pgrid, 256, GEMM_SMEM>>>(en, down_w, vb, nullptr, w1_W, w1_b, rb);
    attn_sparse_kernel<<<sgrid, 256>>>(vb, down_r, rsp, sidx, smv, hb);
    gemm3_kernel<<<ggrid, 256, GEMM_SMEM>>>(hb, mlp1_W1, mlp1_b1, nullptr, tb, 1);
    gemm3_kernel<<<ggrid, 256, GEMM_SMEM>>>(tb, mlp1_W2, mlp1_b2, rb, x, 1);

    // ---- 4 unmasked blocks (HMMA dense attention) ----
    for (int i = 0; i < 4; ++i) {
        gemm3p_kernel<<<pgrid, 256, GEMM_SMEM>>>(x, pa_w + (size_t)i * HH * HID * VD, vb, vh,
            wi_W + (size_t)i * HID * HID, wi_b + (size_t)i * HID, rb);
        attn_mma_kernel<<<mgrid, 128>>>(md, vh, pa_r + (size_t)i * HH, rsp, hb);
        gemm3_kernel<<<ggrid, 256, GEMM_SMEM>>>(hb, blk_W1 + (size_t)i * HID * HID, blk_b1 + (size_t)i * HID, nullptr, tb, 1);
        gemm3_kernel<<<ggrid, 256, GEMM_SMEM>>>(tb, blk_W2 + (size_t)i * HID * HID, blk_b2 + (size_t)i * HID, rb, x, 1);
    }

    // ---- stage 2 (masked -> sparse; no vh needed) ----
    gemm3p_kernel<<<pgrid, 256, GEMM_SMEM>>>(x, up_w, vb, nullptr, w2_W, w2_b, rb);
    attn_sparse_kernel<<<sgrid, 256>>>(vb, up_r, rsp, sidx, smv, hb);
    gemm3_kernel<<<ggrid, 256, GEMM_SMEM>>>(hb, mlp2_W1, mlp2_b1, nullptr, tb, 1);
    gemm3_kernel<<<ggrid, 256, GEMM_SMEM>>>(tb, mlp2_W2, mlp2_b2, rb, x, 1);

    // ---- decoder ----
    gemm3_kernel<<<ggrid, 256, GEMM_SMEM>>>(x, de_W1, de_b1, nullptr, tb, 1);
    final_kernel<<<BN / 8, 256>>>(tb, de_W2, de_b2, outp);
}